// round 1
// baseline (speedup 1.0000x reference)
#include <cuda_runtime.h>
#include <math.h>

#define NROWS 8192
#define KDIM  300
#define KPAD  304
#define NGRP  101           // labels are 1..100
#define INVT  100.0f        // 1/TEMPERATURE

// ---------------- static device scratch (no allocations allowed) ----------------
__device__ float g_xp [NROWS * KPAD];   // padded x
__device__ float g_W1p[KPAD * KPAD];    // padded W1
__device__ float g_W2p[KPAD * KPAD];    // padded W2
__device__ float g_b1p[KPAD];
__device__ float g_b2p[KPAD];
__device__ float g_h1 [NROWS * KPAD];   // relu(x@W1+b1), padded cols = 0
__device__ float g_f  [NROWS * KPAD];   // h2 then normalized in place
__device__ float g_Epos[NROWS];
__device__ float g_Eneg[NROWS];
__device__ float g_Lpos[NROWS];
__device__ int   g_cnt[NGRP];

// ---------------- prep: pad inputs, zero accumulators ----------------
__global__ void prep_kernel(const float* __restrict__ x,
                            const float* __restrict__ W1, const float* __restrict__ b1,
                            const float* __restrict__ W2, const float* __restrict__ b2)
{
    int idx = blockIdx.x * blockDim.x + threadIdx.x;
    int stride = gridDim.x * blockDim.x;
    for (int i = idx; i < NROWS * KPAD; i += stride) {
        int r = i / KPAD, c = i - r * KPAD;
        g_xp[i] = (c < KDIM) ? x[r * KDIM + c] : 0.0f;
    }
    for (int i = idx; i < KPAD * KPAD; i += stride) {
        int r = i / KPAD, c = i - r * KPAD;
        bool in = (r < KDIM) && (c < KDIM);
        g_W1p[i] = in ? W1[r * KDIM + c] : 0.0f;
        g_W2p[i] = in ? W2[r * KDIM + c] : 0.0f;
    }
    for (int i = idx; i < KPAD; i += stride) {
        g_b1p[i] = (i < KDIM) ? b1[i] : 0.0f;
        g_b2p[i] = (i < KDIM) ? b2[i] : 0.0f;
    }
    for (int i = idx; i < NROWS; i += stride) {
        g_Epos[i] = 0.0f; g_Eneg[i] = 0.0f; g_Lpos[i] = 0.0f;
    }
    for (int i = idx; i < NGRP; i += stride) g_cnt[i] = 0;
}

__global__ void hist_kernel(const int* __restrict__ labels)
{
    int i = blockIdx.x * blockDim.x + threadIdx.x;
    if (i < NROWS) atomicAdd(&g_cnt[labels[i]], 1);
}

// ---------------- MLP GEMM: C = act(A @ B + bias), ld = KPAD everywhere ----------------
// MODE 0: A=g_xp, B=g_W1p, bias=g_b1p, C=g_h1, relu
// MODE 1: A=g_h1, B=g_W2p, bias=g_b2p, C=g_f,  no relu
template <int MODE>
__global__ __launch_bounds__(256, 2) void mlp_gemm_kernel()
{
    const float* __restrict__ A    = (MODE == 0) ? g_xp  : g_h1;
    const float* __restrict__ B    = (MODE == 0) ? g_W1p : g_W2p;
    const float* __restrict__ bias = (MODE == 0) ? g_b1p : g_b2p;
    float* __restrict__ C          = (MODE == 0) ? g_h1  : g_f;
    const int N = KPAD;

    __shared__ float As[8][128];
    __shared__ float Bs[8][128];

    const int tid  = threadIdx.x;
    const int i0   = blockIdx.y * 128;
    const int n0   = blockIdx.x * 128;
    const int tRow = tid >> 4;        // 0..15
    const int tCol = tid & 15;        // 0..15

    const int aRow = tid >> 1, aCol = (tid & 1) * 4;   // A tile: 128 rows x 8 k
    const int bRow = tid >> 5, bCol = (tid & 31) * 4;  // B tile: 8 k x 128 n

    float acc[8][8];
#pragma unroll
    for (int m = 0; m < 8; m++)
#pragma unroll
        for (int n = 0; n < 8; n++) acc[m][n] = 0.0f;

    for (int k0 = 0; k0 < KPAD; k0 += 8) {
        float4 av = *(const float4*)(A + (size_t)(i0 + aRow) * KPAD + k0 + aCol);
        float4 bv = make_float4(0.f, 0.f, 0.f, 0.f);
        if (n0 + bCol < N)
            bv = *(const float4*)(B + (size_t)(k0 + bRow) * KPAD + n0 + bCol);
        As[aCol + 0][aRow] = av.x;
        As[aCol + 1][aRow] = av.y;
        As[aCol + 2][aRow] = av.z;
        As[aCol + 3][aRow] = av.w;
        *(float4*)&Bs[bRow][bCol] = bv;
        __syncthreads();
#pragma unroll
        for (int kk = 0; kk < 8; kk++) {
            float rA[8], rB[8];
            *(float4*)(rA)     = *(const float4*)&As[kk][tRow * 8];
            *(float4*)(rA + 4) = *(const float4*)&As[kk][tRow * 8 + 4];
            *(float4*)(rB)     = *(const float4*)&Bs[kk][tCol * 8];
            *(float4*)(rB + 4) = *(const float4*)&Bs[kk][tCol * 8 + 4];
#pragma unroll
            for (int m = 0; m < 8; m++)
#pragma unroll
                for (int n = 0; n < 8; n++) acc[m][n] = fmaf(rA[m], rB[n], acc[m][n]);
        }
        __syncthreads();
    }

#pragma unroll
    for (int m = 0; m < 8; m++) {
        int r = i0 + tRow * 8 + m;
#pragma unroll
        for (int n = 0; n < 8; n++) {
            int c = n0 + tCol * 8 + n;
            if (c < N) {
                float v = acc[m][n] + bias[c];
                if (MODE == 0) v = fmaxf(v, 0.0f);
                C[(size_t)r * KPAD + c] = v;
            }
        }
    }
}

// ---------------- row L2-normalize in place ----------------
__global__ void norm_kernel()
{
    int row = blockIdx.x;
    float* p = g_f + (size_t)row * KPAD;
    float ss = 0.0f;
    for (int c = threadIdx.x; c < KPAD; c += blockDim.x) { float v = p[c]; ss += v * v; }
    __shared__ float s[4];
#pragma unroll
    for (int off = 16; off > 0; off >>= 1) ss += __shfl_down_sync(0xffffffffu, ss, off);
    if ((threadIdx.x & 31) == 0) s[threadIdx.x >> 5] = ss;
    __syncthreads();
    float inv = rsqrtf(s[0] + s[1] + s[2] + s[3]);
    for (int c = threadIdx.x; c < KPAD; c += blockDim.x) p[c] *= inv;
}

// ---------------- contrast kernel: fused f@f^T + exp/mask row-accumulate ----------------
#define JSPLIT 4
__global__ __launch_bounds__(256, 2) void contrast_kernel(const int* __restrict__ labels)
{
    __shared__ float As[8][128];
    __shared__ float Bs[8][128];
    __shared__ int   labi_s[128];
    __shared__ int   labj_s[128];

    const int tid  = threadIdx.x;
    const int i0   = blockIdx.y * 128;
    const int tRow = tid >> 4;
    const int tCol = tid & 15;
    const int ldRow = tid >> 1, ldCol = (tid & 1) * 4;

    if (tid < 128) labi_s[tid] = labels[i0 + tid];

    float Ep[8], En[8], Lp[8];
#pragma unroll
    for (int m = 0; m < 8; m++) { Ep[m] = 0.f; En[m] = 0.f; Lp[m] = 0.f; }

    const int jt_begin = blockIdx.x * (64 / JSPLIT);
    const int jt_end   = jt_begin + (64 / JSPLIT);

    for (int jt = jt_begin; jt < jt_end; jt++) {
        const int j0 = jt * 128;
        __syncthreads();                    // protect labj_s + smem tiles from prior iter
        if (tid < 128) labj_s[tid] = labels[j0 + tid];

        float acc[8][8];
#pragma unroll
        for (int m = 0; m < 8; m++)
#pragma unroll
            for (int n = 0; n < 8; n++) acc[m][n] = 0.0f;

        for (int k0 = 0; k0 < KPAD; k0 += 8) {
            float4 av = *(const float4*)(g_f + (size_t)(i0 + ldRow) * KPAD + k0 + ldCol);
            float4 bv = *(const float4*)(g_f + (size_t)(j0 + ldRow) * KPAD + k0 + ldCol);
            As[ldCol + 0][ldRow] = av.x;
            As[ldCol + 1][ldRow] = av.y;
            As[ldCol + 2][ldRow] = av.z;
            As[ldCol + 3][ldRow] = av.w;
            Bs[ldCol + 0][ldRow] = bv.x;
            Bs[ldCol + 1][ldRow] = bv.y;
            Bs[ldCol + 2][ldRow] = bv.z;
            Bs[ldCol + 3][ldRow] = bv.w;
            __syncthreads();
#pragma unroll
            for (int kk = 0; kk < 8; kk++) {
                float rA[8], rB[8];
                *(float4*)(rA)     = *(const float4*)&As[kk][tRow * 8];
                *(float4*)(rA + 4) = *(const float4*)&As[kk][tRow * 8 + 4];
                *(float4*)(rB)     = *(const float4*)&Bs[kk][tCol * 8];
                *(float4*)(rB + 4) = *(const float4*)&Bs[kk][tCol * 8 + 4];
#pragma unroll
                for (int m = 0; m < 8; m++)
#pragma unroll
                    for (int n = 0; n < 8; n++) acc[m][n] = fmaf(rA[m], rB[n], acc[m][n]);
            }
            __syncthreads();
        }

        // fused epilogue: logits shift by constant 100 (mathematically invariant)
#pragma unroll
        for (int m = 0; m < 8; m++) {
            const int i  = i0 + tRow * 8 + m;
            const int li = labi_s[tRow * 8 + m];
#pragma unroll
            for (int n = 0; n < 8; n++) {
                const int j = j0 + tCol * 8 + n;
                float t = fmaf(acc[m][n], INVT, -INVT);   // logit - 100
                float e = __expf(t);
                bool diag  = (j == i);
                bool match = (labj_s[tCol * 8 + n] == li);
                if (!diag) {
                    if (match) { Ep[m] += e; Lp[m] += t; }
                    else       { En[m] += e; }
                }
            }
        }
    }

    // reduce the 16 column-threads of each row, then atomically accumulate
#pragma unroll
    for (int m = 0; m < 8; m++) {
        float ep = Ep[m], en = En[m], lp = Lp[m];
#pragma unroll
        for (int off = 8; off > 0; off >>= 1) {
            ep += __shfl_down_sync(0xffffffffu, ep, off, 16);
            en += __shfl_down_sync(0xffffffffu, en, off, 16);
            lp += __shfl_down_sync(0xffffffffu, lp, off, 16);
        }
        if (tCol == 0) {
            int i = i0 + tRow * 8 + m;
            atomicAdd(&g_Epos[i], ep);
            atomicAdd(&g_Eneg[i], en);
            atomicAdd(&g_Lpos[i], lp);
        }
    }
}

// ---------------- final loss reduction ----------------
__global__ void loss_kernel(const int* __restrict__ labels, float* __restrict__ out)
{
    __shared__ float ssum[32], scnt[32];
    int tid = threadIdx.x;
    float local = 0.0f, cnt = 0.0f;
    for (int i = tid; i < NROWS; i += blockDim.x) {
        int pc = g_cnt[labels[i]] - 1;
        if (pc > 0) {
            int nc = NROWS - 1 - pc;
            float fpc = (float)pc;
            float Ep = g_Epos[i], En = g_Eneg[i], Lp = g_Lpos[i];
            float denom = Ep / fpc + ((nc > 0) ? En / (float)nc : En);
            float mean  = Lp / fpc - logf(fpc) - logf(denom);
            local += mean;
            cnt += 1.0f;
        }
    }
#pragma unroll
    for (int off = 16; off > 0; off >>= 1) {
        local += __shfl_down_sync(0xffffffffu, local, off);
        cnt   += __shfl_down_sync(0xffffffffu, cnt, off);
    }
    if ((tid & 31) == 0) { ssum[tid >> 5] = local; scnt[tid >> 5] = cnt; }
    __syncthreads();
    if (tid < 32) {
        int nw = blockDim.x >> 5;
        float a = (tid < nw) ? ssum[tid] : 0.0f;
        float b = (tid < nw) ? scnt[tid] : 0.0f;
#pragma unroll
        for (int off = 16; off > 0; off >>= 1) {
            a += __shfl_down_sync(0xffffffffu, a, off);
            b += __shfl_down_sync(0xffffffffu, b, off);
        }
        if (tid == 0) out[0] = -0.01f * (a / b);
    }
}

// ---------------- launch ----------------
extern "C" void kernel_launch(void* const* d_in, const int* in_sizes, int n_in,
                              void* d_out, int out_size)
{
    const float* x      = (const float*)d_in[0];
    const float* W1     = (const float*)d_in[1];
    const float* b1     = (const float*)d_in[2];
    const float* W2     = (const float*)d_in[3];
    const float* b2     = (const float*)d_in[4];
    const int*   labels = (const int*)d_in[5];
    float* out = (float*)d_out;

    prep_kernel<<<256, 256>>>(x, W1, b1, W2, b2);
    hist_kernel<<<(NROWS + 255) / 256, 256>>>(labels);

    dim3 gm((KPAD + 127) / 128, NROWS / 128);   // (3, 64)
    mlp_gemm_kernel<0><<<gm, 256>>>();
    mlp_gemm_kernel<1><<<gm, 256>>>();

    norm_kernel<<<NROWS, 128>>>();

    dim3 gc(JSPLIT, NROWS / 128);               // (4, 64)
    contrast_kernel<<<gc, 256>>>(labels);

    loss_kernel<<<1, 1024>>>(labels, out);
}

// round 3
// speedup vs baseline: 2.9409x; 2.9409x over previous
#include <cuda_runtime.h>
#include <math.h>
#include <stdint.h>

#define NROWS 8192
#define KDIM  300
#define KPAD  320           // 10 chunks of 32
#define NCHUNK 10
#define NGRP  101
#define SSTR  36            // smem row stride in words (pad 32 -> 36)
#define BUFW  (128 * SSTR)  // words per (matrix, buffer)

// ---------------- static device scratch ----------------
__device__ float g_xp [NROWS * KPAD];
__device__ float g_W1p[KPAD * KPAD];
__device__ float g_W2p[KPAD * KPAD];
__device__ float g_b1p[KPAD];
__device__ float g_b2p[KPAD];
__device__ float g_h1 [NROWS * KPAD];
__device__ float g_f  [NROWS * KPAD];
__device__ float g_Epos[NROWS];
__device__ float g_Eneg[NROWS];
__device__ float g_Lpos[NROWS];
__device__ int   g_cnt[NGRP];

// ---------------- helpers ----------------
__device__ __forceinline__ uint32_t f2tf32(float f) {
    uint32_t u;
    asm("cvt.rna.tf32.f32 %0, %1;" : "=r"(u) : "f"(f));
    return u;
}

__device__ __forceinline__ void mma_tf32(float* d, const uint32_t* a, const uint32_t* b) {
    asm volatile(
        "mma.sync.aligned.m16n8k8.row.col.f32.tf32.tf32.f32 "
        "{%0,%1,%2,%3}, {%4,%5,%6,%7}, {%8,%9}, {%0,%1,%2,%3};"
        : "+f"(d[0]), "+f"(d[1]), "+f"(d[2]), "+f"(d[3])
        : "r"(a[0]), "r"(a[1]), "r"(a[2]), "r"(a[3]), "r"(b[0]), "r"(b[1]));
}

// ---------------- prep: pad inputs, zero accumulators ----------------
__global__ void prep_kernel(const float* __restrict__ x,
                            const float* __restrict__ W1, const float* __restrict__ b1,
                            const float* __restrict__ W2, const float* __restrict__ b2)
{
    int idx = blockIdx.x * blockDim.x + threadIdx.x;
    int stride = gridDim.x * blockDim.x;
    for (int i = idx; i < NROWS * KPAD; i += stride) {
        int r = i / KPAD, c = i - r * KPAD;
        g_xp[i] = (c < KDIM) ? x[r * KDIM + c] : 0.0f;
    }
    for (int i = idx; i < KPAD * KPAD; i += stride) {
        int r = i / KPAD, c = i - r * KPAD;
        bool in = (r < KDIM) && (c < KDIM);
        g_W1p[i] = in ? W1[r * KDIM + c] : 0.0f;
        g_W2p[i] = in ? W2[r * KDIM + c] : 0.0f;
    }
    for (int i = idx; i < KPAD; i += stride) {
        g_b1p[i] = (i < KDIM) ? b1[i] : 0.0f;
        g_b2p[i] = (i < KDIM) ? b2[i] : 0.0f;
    }
    for (int i = idx; i < NROWS; i += stride) {
        g_Epos[i] = 0.0f; g_Eneg[i] = 0.0f; g_Lpos[i] = 0.0f;
    }
    for (int i = idx; i < NGRP; i += stride) g_cnt[i] = 0;
}

__global__ void hist_kernel(const int* __restrict__ labels)
{
    int i = blockIdx.x * blockDim.x + threadIdx.x;
    if (i < NROWS) atomicAdd(&g_cnt[labels[i]], 1);
}

// ---------------- MLP GEMM (fp32, unchanged) ----------------
template <int MODE>
__global__ __launch_bounds__(256, 2) void mlp_gemm_kernel()
{
    const float* __restrict__ A    = (MODE == 0) ? g_xp  : g_h1;
    const float* __restrict__ B    = (MODE == 0) ? g_W1p : g_W2p;
    const float* __restrict__ bias = (MODE == 0) ? g_b1p : g_b2p;
    float* __restrict__ C          = (MODE == 0) ? g_h1  : g_f;
    const int N = KPAD;

    __shared__ float As[8][128];
    __shared__ float Bs[8][128];

    const int tid  = threadIdx.x;
    const int i0   = blockIdx.y * 128;
    const int n0   = blockIdx.x * 128;
    const int tRow = tid >> 4;
    const int tCol = tid & 15;

    const int aRow = tid >> 1, aCol = (tid & 1) * 4;
    const int bRow = tid >> 5, bCol = (tid & 31) * 4;

    float acc[8][8];
#pragma unroll
    for (int m = 0; m < 8; m++)
#pragma unroll
        for (int n = 0; n < 8; n++) acc[m][n] = 0.0f;

    for (int k0 = 0; k0 < KPAD; k0 += 8) {
        float4 av = *(const float4*)(A + (size_t)(i0 + aRow) * KPAD + k0 + aCol);
        float4 bv = make_float4(0.f, 0.f, 0.f, 0.f);
        if (n0 + bCol < N)
            bv = *(const float4*)(B + (size_t)(k0 + bRow) * KPAD + n0 + bCol);
        As[aCol + 0][aRow] = av.x;
        As[aCol + 1][aRow] = av.y;
        As[aCol + 2][aRow] = av.z;
        As[aCol + 3][aRow] = av.w;
        *(float4*)&Bs[bRow][bCol] = bv;
        __syncthreads();
#pragma unroll
        for (int kk = 0; kk < 8; kk++) {
            float rA[8], rB[8];
            *(float4*)(rA)     = *(const float4*)&As[kk][tRow * 8];
            *(float4*)(rA + 4) = *(const float4*)&As[kk][tRow * 8 + 4];
            *(float4*)(rB)     = *(const float4*)&Bs[kk][tCol * 8];
            *(float4*)(rB + 4) = *(const float4*)&Bs[kk][tCol * 8 + 4];
#pragma unroll
            for (int m = 0; m < 8; m++)
#pragma unroll
                for (int n = 0; n < 8; n++) acc[m][n] = fmaf(rA[m], rB[n], acc[m][n]);
        }
        __syncthreads();
    }

#pragma unroll
    for (int m = 0; m < 8; m++) {
        int r = i0 + tRow * 8 + m;
#pragma unroll
        for (int n = 0; n < 8; n++) {
            int c = n0 + tCol * 8 + n;
            if (c < N) {
                float v = acc[m][n] + bias[c];
                if (MODE == 0) v = fmaxf(v, 0.0f);
                C[(size_t)r * KPAD + c] = v;
            }
        }
    }
}

// ---------------- row L2-normalize in place ----------------
__global__ void norm_kernel()
{
    int row = blockIdx.x;
    float* p = g_f + (size_t)row * KPAD;
    float ss = 0.0f;
    for (int c = threadIdx.x; c < KPAD; c += blockDim.x) { float v = p[c]; ss += v * v; }
    __shared__ float s[4];
#pragma unroll
    for (int off = 16; off > 0; off >>= 1) ss += __shfl_down_sync(0xffffffffu, ss, off);
    if ((threadIdx.x & 31) == 0) s[threadIdx.x >> 5] = ss;
    __syncthreads();
    float inv = rsqrtf(s[0] + s[1] + s[2] + s[3]);
    for (int c = threadIdx.x; c < KPAD; c += blockDim.x) p[c] *= inv;
}

// ---------------- contrast kernel: mma.sync tf32, symmetric tiles ----------------
// Only upper-triangular tiles (bj >= bi). Row sums -> rows i; col sums -> rows j.
// K interleave within each 8-group: k stored at position (k<4 ? 2k : 2(k-4)+1),
// identical for A and B => dot products unchanged, fragments become LDS.64.
#define CON_SMEM_BYTES ((4 * BUFW) * 4 + 256 * 4 + 768 * 4)

__global__ __launch_bounds__(256) void contrast_mma_kernel(const int* __restrict__ labels)
{
    const int bj = blockIdx.x, bi = blockIdx.y;
    if (bj < bi) return;
    const int i0 = bi * 128, j0 = bj * 128;
    const bool diag = (bi == bj);

    extern __shared__ float sm[];
    float* bufA = sm;                       // [2][BUFW]
    float* bufB = sm + 2 * BUFW;            // [2][BUFW]
    int*   labi_s = (int*)(sm + 4 * BUFW);  // 128
    int*   labj_s = labi_s + 128;           // 128
    float* rEp = (float*)(labj_s + 128);    // 6 x 128 partials
    float* rEn = rEp + 128;
    float* rLp = rEp + 256;
    float* cEp = rEp + 384;
    float* cEn = rEp + 512;
    float* cLp = rEp + 640;

    const int tid  = threadIdx.x;
    const int wid  = tid >> 5;
    const int lane = tid & 31;
    const int g    = lane >> 2;     // 0..7
    const int cl   = lane & 3;      // 0..3
    const int wm   = (wid & 3) * 32;
    const int wn   = (wid >> 2) * 64;

    if (tid < 128) labi_s[tid] = labels[i0 + tid];
    else           labj_s[tid - 128] = labels[j0 + tid - 128];
    for (int t = tid; t < 768; t += 256) rEp[t] = 0.0f;

    const int lrow = tid >> 2;      // 0..63
    const int lgrp = tid & 3;       // 0..3 (8-k group within chunk)

    float4 pa[2][2], pb[2][2];
    {
        const float* gA = g_f + (size_t)(i0 + lrow) * KPAD + lgrp * 8;
        const float* gB = g_f + (size_t)(j0 + lrow) * KPAD + lgrp * 8;
        pa[0][0] = *(const float4*)gA; pa[0][1] = *(const float4*)(gA + 4);
        pb[0][0] = *(const float4*)gB; pb[0][1] = *(const float4*)(gB + 4);
        gA += (size_t)64 * KPAD; gB += (size_t)64 * KPAD;
        pa[1][0] = *(const float4*)gA; pa[1][1] = *(const float4*)(gA + 4);
        pb[1][0] = *(const float4*)gB; pb[1][1] = *(const float4*)(gB + 4);
    }

    float acc[2][8][4];
#pragma unroll
    for (int mt = 0; mt < 2; mt++)
#pragma unroll
        for (int nt = 0; nt < 8; nt++)
#pragma unroll
            for (int v = 0; v < 4; v++) acc[mt][nt][v] = 0.0f;

    for (int c = 0; c < NCHUNK; ++c) {
        const int b = c & 1;
        // store prefetched chunk into smem with tf32 rounding + k-interleave
#pragma unroll
        for (int cc = 0; cc < 2; ++cc) {
            const int row = lrow + 64 * cc;
            float* dA = bufA + b * BUFW + row * SSTR + lgrp * 8;
            float* dB = bufB + b * BUFW + row * SSTR + lgrp * 8;
            const float* alo = (const float*)&pa[cc][0];
            const float* ahi = (const float*)&pa[cc][1];
            const float* blo = (const float*)&pb[cc][0];
            const float* bhi = (const float*)&pb[cc][1];
#pragma unroll
            for (int s = 0; s < 4; ++s) {
                uint2 va = make_uint2(f2tf32(alo[s]), f2tf32(ahi[s]));
                *(uint2*)(dA + 2 * s) = va;
                uint2 vb = make_uint2(f2tf32(blo[s]), f2tf32(bhi[s]));
                *(uint2*)(dB + 2 * s) = vb;
            }
        }
        __syncthreads();
        if (c + 1 < NCHUNK) {
            const float* gA = g_f + (size_t)(i0 + lrow) * KPAD + (c + 1) * 32 + lgrp * 8;
            const float* gB = g_f + (size_t)(j0 + lrow) * KPAD + (c + 1) * 32 + lgrp * 8;
            pa[0][0] = *(const float4*)gA; pa[0][1] = *(const float4*)(gA + 4);
            pb[0][0] = *(const float4*)gB; pb[0][1] = *(const float4*)(gB + 4);
            gA += (size_t)64 * KPAD; gB += (size_t)64 * KPAD;
            pa[1][0] = *(const float4*)gA; pa[1][1] = *(const float4*)(gA + 4);
            pb[1][0] = *(const float4*)gB; pb[1][1] = *(const float4*)(gB + 4);
        }
        const float* A = bufA + b * BUFW;
        const float* B = bufB + b * BUFW;
#pragma unroll
        for (int kk = 0; kk < 4; ++kk) {
            uint32_t af[2][4];
#pragma unroll
            for (int mt = 0; mt < 2; ++mt) {
                const int r = wm + mt * 16 + g;
                uint2 lo = *(const uint2*)(A + r * SSTR + kk * 8 + 2 * cl);
                uint2 hi = *(const uint2*)(A + (r + 8) * SSTR + kk * 8 + 2 * cl);
                af[mt][0] = lo.x; af[mt][2] = lo.y;
                af[mt][1] = hi.x; af[mt][3] = hi.y;
            }
#pragma unroll
            for (int nt = 0; nt < 8; ++nt) {
                const int n = wn + nt * 8 + g;
                uint2 bv = *(const uint2*)(B + n * SSTR + kk * 8 + 2 * cl);
                uint32_t bf[2] = { bv.x, bv.y };
                mma_tf32(acc[0][nt], af[0], bf);
                mma_tf32(acc[1][nt], af[1], bf);
            }
        }
        __syncthreads();
    }

    // ---- fused epilogue ----
    float rp[4][3];
#pragma unroll
    for (int u = 0; u < 4; u++) { rp[u][0] = 0.f; rp[u][1] = 0.f; rp[u][2] = 0.f; }

#pragma unroll
    for (int nt = 0; nt < 8; ++nt) {
        float cs[2][3] = { {0.f,0.f,0.f}, {0.f,0.f,0.f} };
#pragma unroll
        for (int mt = 0; mt < 2; ++mt)
#pragma unroll
            for (int h = 0; h < 2; ++h)
#pragma unroll
                for (int q = 0; q < 2; ++q) {
                    const int r   = wm + mt * 16 + h * 8 + g;
                    const int col = wn + nt * 8 + 2 * cl + q;
                    float t = fmaf(acc[mt][nt][h * 2 + q], 100.0f, -100.0f);
                    float e = __expf(t);
                    bool self  = diag && (r == col);
                    bool match = (labi_s[r] == labj_s[col]);
                    if (!self) {
                        if (match) { rp[mt * 2 + h][0] += e; rp[mt * 2 + h][2] += t;
                                     cs[q][0] += e;          cs[q][2] += t; }
                        else       { rp[mt * 2 + h][1] += e; cs[q][1] += e; }
                    }
                }
        if (!diag) {
#pragma unroll
            for (int q = 0; q < 2; ++q)
#pragma unroll
                for (int v = 0; v < 3; ++v) {
                    float x = cs[q][v];
                    x += __shfl_xor_sync(0xffffffffu, x, 4);
                    x += __shfl_xor_sync(0xffffffffu, x, 8);
                    x += __shfl_xor_sync(0xffffffffu, x, 16);
                    cs[q][v] = x;
                }
            if (g == 0) {
                const int col = wn + nt * 8 + 2 * cl;
                atomicAdd(&cEp[col],     cs[0][0]);
                atomicAdd(&cEn[col],     cs[0][1]);
                atomicAdd(&cLp[col],     cs[0][2]);
                atomicAdd(&cEp[col + 1], cs[1][0]);
                atomicAdd(&cEn[col + 1], cs[1][1]);
                atomicAdd(&cLp[col + 1], cs[1][2]);
            }
        }
    }
#pragma unroll
    for (int u = 0; u < 4; ++u) {
#pragma unroll
        for (int v = 0; v < 3; ++v) {
            float x = rp[u][v];
            x += __shfl_xor_sync(0xffffffffu, x, 1);
            x += __shfl_xor_sync(0xffffffffu, x, 2);
            rp[u][v] = x;
        }
        if (cl == 0) {
            const int r = wm + (u >> 1) * 16 + (u & 1) * 8 + g;
            atomicAdd(&rEp[r], rp[u][0]);
            atomicAdd(&rEn[r], rp[u][1]);
            atomicAdd(&rLp[r], rp[u][2]);
        }
    }
    __syncthreads();
    if (tid < 128) {
        atomicAdd(&g_Epos[i0 + tid], rEp[tid]);
        atomicAdd(&g_Eneg[i0 + tid], rEn[tid]);
        atomicAdd(&g_Lpos[i0 + tid], rLp[tid]);
        if (!diag) {
            atomicAdd(&g_Epos[j0 + tid], cEp[tid]);
            atomicAdd(&g_Eneg[j0 + tid], cEn[tid]);
            atomicAdd(&g_Lpos[j0 + tid], cLp[tid]);
        }
    }
}

// ---------------- final loss reduction ----------------
__global__ void loss_kernel(const int* __restrict__ labels, float* __restrict__ out)
{
    __shared__ float ssum[32], scnt[32];
    int tid = threadIdx.x;
    float local = 0.0f, cnt = 0.0f;
    for (int i = tid; i < NROWS; i += blockDim.x) {
        int pc = g_cnt[labels[i]] - 1;
        if (pc > 0) {
            int nc = NROWS - 1 - pc;
            float fpc = (float)pc;
            float Ep = g_Epos[i], En = g_Eneg[i], Lp = g_Lpos[i];
            float denom = Ep / fpc + ((nc > 0) ? En / (float)nc : En);
            float mean  = Lp / fpc - logf(fpc) - logf(denom);
            local += mean;
            cnt += 1.0f;
        }
    }
#pragma unroll
    for (int off = 16; off > 0; off >>= 1) {
        local += __shfl_down_sync(0xffffffffu, local, off);
        cnt   += __shfl_down_sync(0xffffffffu, cnt, off);
    }
    if ((tid & 31) == 0) { ssum[tid >> 5] = local; scnt[tid >> 5] = cnt; }
    __syncthreads();
    if (tid < 32) {
        int nw = blockDim.x >> 5;
        float a = (tid < nw) ? ssum[tid] : 0.0f;
        float b = (tid < nw) ? scnt[tid] : 0.0f;
#pragma unroll
        for (int off = 16; off > 0; off >>= 1) {
            a += __shfl_down_sync(0xffffffffu, a, off);
            b += __shfl_down_sync(0xffffffffu, b, off);
        }
        if (tid == 0) out[0] = -0.01f * (a / b);
    }
}

// ---------------- launch ----------------
extern "C" void kernel_launch(void* const* d_in, const int* in_sizes, int n_in,
                              void* d_out, int out_size)
{
    const float* x      = (const float*)d_in[0];
    const float* W1     = (const float*)d_in[1];
    const float* b1     = (const float*)d_in[2];
    const float* W2     = (const float*)d_in[3];
    const float* b2     = (const float*)d_in[4];
    const int*   labels = (const int*)d_in[5];
    float* out = (float*)d_out;

    static int smem_set = 0;
    if (!smem_set) {
        cudaFuncSetAttribute(contrast_mma_kernel,
                             cudaFuncAttributeMaxDynamicSharedMemorySize, CON_SMEM_BYTES);
        smem_set = 1;
    }

    prep_kernel<<<256, 256>>>(x, W1, b1, W2, b2);
    hist_kernel<<<(NROWS + 255) / 256, 256>>>(labels);

    dim3 gm((KPAD + 127) / 128, NROWS / 128);
    mlp_gemm_kernel<0><<<gm, 256>>>();
    mlp_gemm_kernel<1><<<gm, 256>>>();

    norm_kernel<<<NROWS, 128>>>();

    dim3 gc(NROWS / 128, NROWS / 128);   // (64, 64), lower triangle exits early
    contrast_mma_kernel<<<gc, 256, CON_SMEM_BYTES>>>(labels);

    loss_kernel<<<1, 1024>>>(labels, out);
}

// round 4
// speedup vs baseline: 3.9193x; 1.3327x over previous
#include <cuda_runtime.h>
#include <math.h>
#include <stdint.h>

#define NROWS 8192
#define KDIM  300
#define KPAD  320           // 10 chunks of 32
#define NCHUNK 10
#define NGRP  101
#define SSTR  36            // smem row stride in words (pad 32 -> 36)
#define BUFW  (128 * SSTR)  // words per (matrix, buffer) in contrast kernel

// ---------------- static device scratch ----------------
__device__ float g_xp [NROWS * KPAD];
__device__ float g_W1t[KPAD * KPAD];    // transposed: [n][k]
__device__ float g_W2t[KPAD * KPAD];    // transposed: [n][k]
__device__ float g_b1p[KPAD];
__device__ float g_b2p[KPAD];
__device__ float g_h1 [NROWS * KPAD];
__device__ float g_f  [NROWS * KPAD];
__device__ float g_ss [NROWS];          // row sum-of-squares of h2
__device__ float g_Epos[NROWS];
__device__ float g_Eneg[NROWS];
__device__ float g_Lpos[NROWS];
__device__ int   g_cnt[NGRP];

// ---------------- helpers ----------------
__device__ __forceinline__ uint32_t f2tf32(float f) {
    uint32_t u;
    asm("cvt.rna.tf32.f32 %0, %1;" : "=r"(u) : "f"(f));
    return u;
}

__device__ __forceinline__ void mma_tf32(float* d, const uint32_t* a, const uint32_t* b) {
    asm volatile(
        "mma.sync.aligned.m16n8k8.row.col.f32.tf32.tf32.f32 "
        "{%0,%1,%2,%3}, {%4,%5,%6,%7}, {%8,%9}, {%0,%1,%2,%3};"
        : "+f"(d[0]), "+f"(d[1]), "+f"(d[2]), "+f"(d[3])
        : "r"(a[0]), "r"(a[1]), "r"(a[2]), "r"(a[3]), "r"(b[0]), "r"(b[1]));
}

// ---------------- prep: pad x, transpose+pad W, zero accumulators ----------------
__global__ void prep_kernel(const float* __restrict__ x,
                            const float* __restrict__ W1, const float* __restrict__ b1,
                            const float* __restrict__ W2, const float* __restrict__ b2)
{
    int idx = blockIdx.x * blockDim.x + threadIdx.x;
    int stride = gridDim.x * blockDim.x;
    for (int i = idx; i < NROWS * KPAD; i += stride) {
        int r = i / KPAD, c = i - r * KPAD;
        g_xp[i] = (c < KDIM) ? x[r * KDIM + c] : 0.0f;
    }
    for (int i = idx; i < KPAD * KPAD; i += stride) {
        int n = i / KPAD, k = i - n * KPAD;
        bool in = (n < KDIM) && (k < KDIM);
        g_W1t[i] = in ? W1[k * KDIM + n] : 0.0f;
        g_W2t[i] = in ? W2[k * KDIM + n] : 0.0f;
    }
    for (int i = idx; i < KPAD; i += stride) {
        g_b1p[i] = (i < KDIM) ? b1[i] : 0.0f;
        g_b2p[i] = (i < KDIM) ? b2[i] : 0.0f;
    }
    for (int i = idx; i < NROWS; i += stride) {
        g_Epos[i] = 0.0f; g_Eneg[i] = 0.0f; g_Lpos[i] = 0.0f; g_ss[i] = 0.0f;
    }
    for (int i = idx; i < NGRP; i += stride) g_cnt[i] = 0;
}

__global__ void hist_kernel(const int* __restrict__ labels)
{
    int i = blockIdx.x * blockDim.x + threadIdx.x;
    if (i < NROWS) atomicAdd(&g_cnt[labels[i]], 1);
}

// ---------------- MLP GEMM on tensor cores (tf32 mma.sync) ----------------
// C[128 x 64] tile per CTA. A row-major K-major, Bt row-major K-major (col operand).
// MODE 0: A=g_xp,  B=g_W1t, bias=g_b1p, relu -> g_h1
// MODE 1: A=g_h1,  B=g_W2t, bias=g_b2p       -> g_f, + row ss atomics
#define MLP_AW   (128 * SSTR)
#define MLP_BW   (64 * SSTR)
#define MLP_SMEM ((2 * MLP_AW + 2 * MLP_BW) * 4)

template <int MODE>
__global__ __launch_bounds__(256) void mlp_tc_kernel()
{
    const float* __restrict__ A    = (MODE == 0) ? g_xp  : g_h1;
    const float* __restrict__ Bt   = (MODE == 0) ? g_W1t : g_W2t;
    const float* __restrict__ bias = (MODE == 0) ? g_b1p : g_b2p;
    float* __restrict__ C          = (MODE == 0) ? g_h1  : g_f;

    extern __shared__ float sm[];
    float* bufA = sm;                   // [2][MLP_AW]
    float* bufB = sm + 2 * MLP_AW;      // [2][MLP_BW]

    const int tid  = threadIdx.x;
    const int wid  = tid >> 5;
    const int lane = tid & 31;
    const int g    = lane >> 2;
    const int cl   = lane & 3;
    const int wm   = (wid & 3) * 32;
    const int wn   = (wid >> 2) * 32;
    const int i0   = blockIdx.y * 128;
    const int n0   = blockIdx.x * 64;

    const int lrow = tid >> 2;          // 0..63
    const int lgrp = tid & 3;

    float4 pa[2][2], pb[2];
    {
        const float* gA = A + (size_t)(i0 + lrow) * KPAD + lgrp * 8;
        pa[0][0] = *(const float4*)gA; pa[0][1] = *(const float4*)(gA + 4);
        gA += (size_t)64 * KPAD;
        pa[1][0] = *(const float4*)gA; pa[1][1] = *(const float4*)(gA + 4);
        const float* gB = Bt + (size_t)(n0 + lrow) * KPAD + lgrp * 8;
        pb[0] = *(const float4*)gB; pb[1] = *(const float4*)(gB + 4);
    }

    float acc[2][4][4];
#pragma unroll
    for (int mt = 0; mt < 2; mt++)
#pragma unroll
        for (int nt = 0; nt < 4; nt++)
#pragma unroll
            for (int v = 0; v < 4; v++) acc[mt][nt][v] = 0.0f;

    for (int c = 0; c < NCHUNK; ++c) {
        const int b = c & 1;
#pragma unroll
        for (int cc = 0; cc < 2; ++cc) {
            float* dA = bufA + b * MLP_AW + (lrow + 64 * cc) * SSTR + lgrp * 8;
            const float* alo = (const float*)&pa[cc][0];
            const float* ahi = (const float*)&pa[cc][1];
#pragma unroll
            for (int s = 0; s < 4; ++s)
                *(uint2*)(dA + 2 * s) = make_uint2(f2tf32(alo[s]), f2tf32(ahi[s]));
        }
        {
            float* dB = bufB + b * MLP_BW + lrow * SSTR + lgrp * 8;
            const float* blo = (const float*)&pb[0];
            const float* bhi = (const float*)&pb[1];
#pragma unroll
            for (int s = 0; s < 4; ++s)
                *(uint2*)(dB + 2 * s) = make_uint2(f2tf32(blo[s]), f2tf32(bhi[s]));
        }
        __syncthreads();
        if (c + 1 < NCHUNK) {
            const float* gA = A + (size_t)(i0 + lrow) * KPAD + (c + 1) * 32 + lgrp * 8;
            pa[0][0] = *(const float4*)gA; pa[0][1] = *(const float4*)(gA + 4);
            gA += (size_t)64 * KPAD;
            pa[1][0] = *(const float4*)gA; pa[1][1] = *(const float4*)(gA + 4);
            const float* gB = Bt + (size_t)(n0 + lrow) * KPAD + (c + 1) * 32 + lgrp * 8;
            pb[0] = *(const float4*)gB; pb[1] = *(const float4*)(gB + 4);
        }
        const float* Ab = bufA + b * MLP_AW;
        const float* Bb = bufB + b * MLP_BW;
#pragma unroll
        for (int kk = 0; kk < 4; ++kk) {
            uint32_t af[2][4];
#pragma unroll
            for (int mt = 0; mt < 2; ++mt) {
                const int r = wm + mt * 16 + g;
                uint2 lo = *(const uint2*)(Ab + r * SSTR + kk * 8 + 2 * cl);
                uint2 hi = *(const uint2*)(Ab + (r + 8) * SSTR + kk * 8 + 2 * cl);
                af[mt][0] = lo.x; af[mt][2] = lo.y;
                af[mt][1] = hi.x; af[mt][3] = hi.y;
            }
#pragma unroll
            for (int nt = 0; nt < 4; ++nt) {
                const int n = wn + nt * 8 + g;
                uint2 bv = *(const uint2*)(Bb + n * SSTR + kk * 8 + 2 * cl);
                uint32_t bf[2] = { bv.x, bv.y };
                mma_tf32(acc[0][nt], af[0], bf);
                mma_tf32(acc[1][nt], af[1], bf);
            }
        }
        __syncthreads();
    }

    // epilogue: bias (+relu) store; MODE 1 also accumulates row sum-of-squares
#pragma unroll
    for (int mt = 0; mt < 2; ++mt) {
#pragma unroll
        for (int h = 0; h < 2; ++h) {
            const int r = i0 + wm + mt * 16 + h * 8 + g;
            float ssum = 0.0f;
#pragma unroll
            for (int nt = 0; nt < 4; ++nt) {
                const int col = n0 + wn + nt * 8 + 2 * cl;
                float v0 = acc[mt][nt][h * 2 + 0] + bias[col];
                float v1 = acc[mt][nt][h * 2 + 1] + bias[col + 1];
                if (MODE == 0) { v0 = fmaxf(v0, 0.0f); v1 = fmaxf(v1, 0.0f); }
                *(float2*)(C + (size_t)r * KPAD + col) = make_float2(v0, v1);
                if (MODE == 1) ssum = fmaf(v0, v0, fmaf(v1, v1, ssum));
            }
            if (MODE == 1) {
                ssum += __shfl_xor_sync(0xffffffffu, ssum, 1);
                ssum += __shfl_xor_sync(0xffffffffu, ssum, 2);
                if (cl == 0) atomicAdd(&g_ss[r], ssum);
            }
        }
    }
}

// ---------------- row scale by rsqrt(ss) ----------------
__global__ void norm_kernel()
{
    int idx = blockIdx.x * blockDim.x + threadIdx.x;   // float4 index
    const int total = NROWS * (KPAD / 4);
    if (idx < total) {
        int row = idx / (KPAD / 4);
        float inv = rsqrtf(g_ss[row]);
        float4 v = ((const float4*)g_f)[idx];
        v.x *= inv; v.y *= inv; v.z *= inv; v.w *= inv;
        ((float4*)g_f)[idx] = v;
    }
}

// ---------------- contrast kernel: mma.sync tf32, symmetric tiles (unchanged) ----------------
#define CON_SMEM_BYTES ((4 * BUFW) * 4 + 256 * 4 + 768 * 4)

__global__ __launch_bounds__(256) void contrast_mma_kernel(const int* __restrict__ labels)
{
    const int bj = blockIdx.x, bi = blockIdx.y;
    if (bj < bi) return;
    const int i0 = bi * 128, j0 = bj * 128;
    const bool diag = (bi == bj);

    extern __shared__ float sm[];
    float* bufA = sm;
    float* bufB = sm + 2 * BUFW;
    int*   labi_s = (int*)(sm + 4 * BUFW);
    int*   labj_s = labi_s + 128;
    float* rEp = (float*)(labj_s + 128);
    float* rEn = rEp + 128;
    float* rLp = rEp + 256;
    float* cEp = rEp + 384;
    float* cEn = rEp + 512;
    float* cLp = rEp + 640;

    const int tid  = threadIdx.x;
    const int wid  = tid >> 5;
    const int lane = tid & 31;
    const int g    = lane >> 2;
    const int cl   = lane & 3;
    const int wm   = (wid & 3) * 32;
    const int wn   = (wid >> 2) * 64;

    if (tid < 128) labi_s[tid] = labels[i0 + tid];
    else           labj_s[tid - 128] = labels[j0 + tid - 128];
    for (int t = tid; t < 768; t += 256) rEp[t] = 0.0f;

    const int lrow = tid >> 2;
    const int lgrp = tid & 3;

    float4 pa[2][2], pb[2][2];
    {
        const float* gA = g_f + (size_t)(i0 + lrow) * KPAD + lgrp * 8;
        const float* gB = g_f + (size_t)(j0 + lrow) * KPAD + lgrp * 8;
        pa[0][0] = *(const float4*)gA; pa[0][1] = *(const float4*)(gA + 4);
        pb[0][0] = *(const float4*)gB; pb[0][1] = *(const float4*)(gB + 4);
        gA += (size_t)64 * KPAD; gB += (size_t)64 * KPAD;
        pa[1][0] = *(const float4*)gA; pa[1][1] = *(const float4*)(gA + 4);
        pb[1][0] = *(const float4*)gB; pb[1][1] = *(const float4*)(gB + 4);
    }

    float acc[2][8][4];
#pragma unroll
    for (int mt = 0; mt < 2; mt++)
#pragma unroll
        for (int nt = 0; nt < 8; nt++)
#pragma unroll
            for (int v = 0; v < 4; v++) acc[mt][nt][v] = 0.0f;

    for (int c = 0; c < NCHUNK; ++c) {
        const int b = c & 1;
#pragma unroll
        for (int cc = 0; cc < 2; ++cc) {
            const int row = lrow + 64 * cc;
            float* dA = bufA + b * BUFW + row * SSTR + lgrp * 8;
            float* dB = bufB + b * BUFW + row * SSTR + lgrp * 8;
            const float* alo = (const float*)&pa[cc][0];
            const float* ahi = (const float*)&pa[cc][1];
            const float* blo = (const float*)&pb[cc][0];
            const float* bhi = (const float*)&pb[cc][1];
#pragma unroll
            for (int s = 0; s < 4; ++s) {
                *(uint2*)(dA + 2 * s) = make_uint2(f2tf32(alo[s]), f2tf32(ahi[s]));
                *(uint2*)(dB + 2 * s) = make_uint2(f2tf32(blo[s]), f2tf32(bhi[s]));
            }
        }
        __syncthreads();
        if (c + 1 < NCHUNK) {
            const float* gA = g_f + (size_t)(i0 + lrow) * KPAD + (c + 1) * 32 + lgrp * 8;
            const float* gB = g_f + (size_t)(j0 + lrow) * KPAD + (c + 1) * 32 + lgrp * 8;
            pa[0][0] = *(const float4*)gA; pa[0][1] = *(const float4*)(gA + 4);
            pb[0][0] = *(const float4*)gB; pb[0][1] = *(const float4*)(gB + 4);
            gA += (size_t)64 * KPAD; gB += (size_t)64 * KPAD;
            pa[1][0] = *(const float4*)gA; pa[1][1] = *(const float4*)(gA + 4);
            pb[1][0] = *(const float4*)gB; pb[1][1] = *(const float4*)(gB + 4);
        }
        const float* A = bufA + b * BUFW;
        const float* B = bufB + b * BUFW;
#pragma unroll
        for (int kk = 0; kk < 4; ++kk) {
            uint32_t af[2][4];
#pragma unroll
            for (int mt = 0; mt < 2; ++mt) {
                const int r = wm + mt * 16 + g;
                uint2 lo = *(const uint2*)(A + r * SSTR + kk * 8 + 2 * cl);
                uint2 hi = *(const uint2*)(A + (r + 8) * SSTR + kk * 8 + 2 * cl);
                af[mt][0] = lo.x; af[mt][2] = lo.y;
                af[mt][1] = hi.x; af[mt][3] = hi.y;
            }
#pragma unroll
            for (int nt = 0; nt < 8; ++nt) {
                const int n = wn + nt * 8 + g;
                uint2 bv = *(const uint2*)(B + n * SSTR + kk * 8 + 2 * cl);
                uint32_t bf[2] = { bv.x, bv.y };
                mma_tf32(acc[0][nt], af[0], bf);
                mma_tf32(acc[1][nt], af[1], bf);
            }
        }
        __syncthreads();
    }

    float rp[4][3];
#pragma unroll
    for (int u = 0; u < 4; u++) { rp[u][0] = 0.f; rp[u][1] = 0.f; rp[u][2] = 0.f; }

#pragma unroll
    for (int nt = 0; nt < 8; ++nt) {
        float cs[2][3] = { {0.f,0.f,0.f}, {0.f,0.f,0.f} };
#pragma unroll
        for (int mt = 0; mt < 2; ++mt)
#pragma unroll
            for (int h = 0; h < 2; ++h)
#pragma unroll
                for (int q = 0; q < 2; ++q) {
                    const int r   = wm + mt * 16 + h * 8 + g;
                    const int col = wn + nt * 8 + 2 * cl + q;
                    float t = fmaf(acc[mt][nt][h * 2 + q], 100.0f, -100.0f);
                    float e = __expf(t);
                    bool self  = diag && (r == col);
                    bool match = (labi_s[r] == labj_s[col]);
                    if (!self) {
                        if (match) { rp[mt * 2 + h][0] += e; rp[mt * 2 + h][2] += t;
                                     cs[q][0] += e;          cs[q][2] += t; }
                        else       { rp[mt * 2 + h][1] += e; cs[q][1] += e; }
                    }
                }
        if (!diag) {
#pragma unroll
            for (int q = 0; q < 2; ++q)
#pragma unroll
                for (int v = 0; v < 3; ++v) {
                    float x = cs[q][v];
                    x += __shfl_xor_sync(0xffffffffu, x, 4);
                    x += __shfl_xor_sync(0xffffffffu, x, 8);
                    x += __shfl_xor_sync(0xffffffffu, x, 16);
                    cs[q][v] = x;
                }
            if (g == 0) {
                const int col = wn + nt * 8 + 2 * cl;
                atomicAdd(&cEp[col],     cs[0][0]);
                atomicAdd(&cEn[col],     cs[0][1]);
                atomicAdd(&cLp[col],     cs[0][2]);
                atomicAdd(&cEp[col + 1], cs[1][0]);
                atomicAdd(&cEn[col + 1], cs[1][1]);
                atomicAdd(&cLp[col + 1], cs[1][2]);
            }
        }
    }
#pragma unroll
    for (int u = 0; u < 4; ++u) {
#pragma unroll
        for (int v = 0; v < 3; ++v) {
            float x = rp[u][v];
            x += __shfl_xor_sync(0xffffffffu, x, 1);
            x += __shfl_xor_sync(0xffffffffu, x, 2);
            rp[u][v] = x;
        }
        if (cl == 0) {
            const int r = wm + (u >> 1) * 16 + (u & 1) * 8 + g;
            atomicAdd(&rEp[r], rp[u][0]);
            atomicAdd(&rEn[r], rp[u][1]);
            atomicAdd(&rLp[r], rp[u][2]);
        }
    }
    __syncthreads();
    if (tid < 128) {
        atomicAdd(&g_Epos[i0 + tid], rEp[tid]);
        atomicAdd(&g_Eneg[i0 + tid], rEn[tid]);
        atomicAdd(&g_Lpos[i0 + tid], rLp[tid]);
        if (!diag) {
            atomicAdd(&g_Epos[j0 + tid], cEp[tid]);
            atomicAdd(&g_Eneg[j0 + tid], cEn[tid]);
            atomicAdd(&g_Lpos[j0 + tid], cLp[tid]);
        }
    }
}

// ---------------- final loss reduction ----------------
__global__ void loss_kernel(const int* __restrict__ labels, float* __restrict__ out)
{
    __shared__ float ssum[32], scnt[32];
    int tid = threadIdx.x;
    float local = 0.0f, cnt = 0.0f;
    for (int i = tid; i < NROWS; i += blockDim.x) {
        int pc = g_cnt[labels[i]] - 1;
        if (pc > 0) {
            int nc = NROWS - 1 - pc;
            float fpc = (float)pc;
            float Ep = g_Epos[i], En = g_Eneg[i], Lp = g_Lpos[i];
            float denom = Ep / fpc + ((nc > 0) ? En / (float)nc : En);
            float mean  = Lp / fpc - logf(fpc) - logf(denom);
            local += mean;
            cnt += 1.0f;
        }
    }
#pragma unroll
    for (int off = 16; off > 0; off >>= 1) {
        local += __shfl_down_sync(0xffffffffu, local, off);
        cnt   += __shfl_down_sync(0xffffffffu, cnt, off);
    }
    if ((tid & 31) == 0) { ssum[tid >> 5] = local; scnt[tid >> 5] = cnt; }
    __syncthreads();
    if (tid < 32) {
        int nw = blockDim.x >> 5;
        float a = (tid < nw) ? ssum[tid] : 0.0f;
        float b = (tid < nw) ? scnt[tid] : 0.0f;
#pragma unroll
        for (int off = 16; off > 0; off >>= 1) {
            a += __shfl_down_sync(0xffffffffu, a, off);
            b += __shfl_down_sync(0xffffffffu, b, off);
        }
        if (tid == 0) out[0] = -0.01f * (a / b);
    }
}

// ---------------- launch ----------------
extern "C" void kernel_launch(void* const* d_in, const int* in_sizes, int n_in,
                              void* d_out, int out_size)
{
    const float* x      = (const float*)d_in[0];
    const float* W1     = (const float*)d_in[1];
    const float* b1     = (const float*)d_in[2];
    const float* W2     = (const float*)d_in[3];
    const float* b2     = (const float*)d_in[4];
    const int*   labels = (const int*)d_in[5];
    float* out = (float*)d_out;

    static int smem_set = 0;
    if (!smem_set) {
        cudaFuncSetAttribute(contrast_mma_kernel,
                             cudaFuncAttributeMaxDynamicSharedMemorySize, CON_SMEM_BYTES);
        cudaFuncSetAttribute(mlp_tc_kernel<0>,
                             cudaFuncAttributeMaxDynamicSharedMemorySize, MLP_SMEM);
        cudaFuncSetAttribute(mlp_tc_kernel<1>,
                             cudaFuncAttributeMaxDynamicSharedMemorySize, MLP_SMEM);
        smem_set = 1;
    }

    prep_kernel<<<256, 256>>>(x, W1, b1, W2, b2);
    hist_kernel<<<(NROWS + 255) / 256, 256>>>(labels);

    dim3 gm(KPAD / 64, NROWS / 128);            // (5, 64)
    mlp_tc_kernel<0><<<gm, 256, MLP_SMEM>>>();
    mlp_tc_kernel<1><<<gm, 256, MLP_SMEM>>>();

    norm_kernel<<<(NROWS * (KPAD / 4) + 255) / 256, 256>>>();

    dim3 gc(NROWS / 128, NROWS / 128);          // (64, 64), lower triangle exits early
    contrast_mma_kernel<<<gc, 256, CON_SMEM_BYTES>>>(labels);

    loss_kernel<<<1, 1024>>>(labels, out);
}

// round 5
// speedup vs baseline: 4.9408x; 1.2606x over previous
#include <cuda_runtime.h>
#include <math.h>
#include <stdint.h>

#define NROWS 8192
#define KDIM  300
#define KPAD  320           // 10 chunks of 32
#define NCHUNK 10
#define NGRP  101
#define SSTR  36            // smem row stride in words
#define BUFW  (128 * SSTR)  // words per (matrix, buffer)

// ---------------- static device scratch ----------------
__device__ float g_xp [NROWS * KPAD];   // tf32-rounded, k-permuted
__device__ float g_W1t[KPAD * KPAD];    // transposed [n][k], tf32-rounded, k-permuted
__device__ float g_W2t[KPAD * KPAD];
__device__ float g_b1p[KPAD];           // unpermuted
__device__ float g_b2p[KPAD];
__device__ float g_h1 [NROWS * KPAD];   // tf32-rounded, k-permuted
__device__ float g_f  [NROWS * KPAD];   // k-permuted; rounded by norm_kernel
__device__ float g_ss [NROWS];
__device__ float g_Epos[NROWS];
__device__ float g_Eneg[NROWS];
__device__ float g_Lpos[NROWS];
__device__ int   g_cnt[NGRP];

// ---------------- helpers ----------------
__device__ __forceinline__ uint32_t f2tf32(float f) {
    uint32_t u;
    asm("cvt.rna.tf32.f32 %0, %1;" : "=r"(u) : "f"(f));
    return u;
}
__device__ __forceinline__ float tf32r(float f) { return __uint_as_float(f2tf32(f)); }

// chunk-local k permutation: k -> position
__device__ __forceinline__ int perm_col(int c) {
    int chunk = c >> 5, w = c & 31;
    int kk = w >> 3, kr = w & 7;
    return chunk * 32 + (kr & 3) * 8 + kk * 2 + (kr >> 2);
}
// position -> k (inverse)
__device__ __forceinline__ int inv_perm_col(int p) {
    int chunk = p >> 5, q = p & 31;
    int rr = q >> 3, rem = q & 7;
    int kk = rem >> 1, qb = rem & 1;
    return chunk * 32 + kk * 8 + (qb * 4 + rr);
}

__device__ __forceinline__ uint32_t smem_u32(const void* p) {
    uint32_t a;
    asm("{ .reg .u64 t; cvta.to.shared.u64 t, %1; cvt.u32.u64 %0, t; }" : "=r"(a) : "l"(p));
    return a;
}
__device__ __forceinline__ void cp_async16(uint32_t dst, const void* src) {
    asm volatile("cp.async.ca.shared.global [%0], [%1], 16;" :: "r"(dst), "l"(src));
}
#define CP_COMMIT() asm volatile("cp.async.commit_group;" ::: "memory")
#define CP_WAIT(n)  asm volatile("cp.async.wait_group %0;" :: "n"(n) : "memory")

__device__ __forceinline__ void mma_tf32(float* d, const uint32_t* a, const uint32_t* b) {
    asm volatile(
        "mma.sync.aligned.m16n8k8.row.col.f32.tf32.tf32.f32 "
        "{%0,%1,%2,%3}, {%4,%5,%6,%7}, {%8,%9}, {%0,%1,%2,%3};"
        : "+f"(d[0]), "+f"(d[1]), "+f"(d[2]), "+f"(d[3])
        : "r"(a[0]), "r"(a[1]), "r"(a[2]), "r"(a[3]), "r"(b[0]), "r"(b[1]));
}

// ---------------- prep ----------------
__global__ void prep_kernel(const float* __restrict__ x,
                            const float* __restrict__ W1, const float* __restrict__ b1,
                            const float* __restrict__ W2, const float* __restrict__ b2)
{
    int idx = blockIdx.x * blockDim.x + threadIdx.x;
    int stride = gridDim.x * blockDim.x;
    for (int i = idx; i < NROWS * KPAD; i += stride) {
        int r = i / KPAD, p = i - r * KPAD;
        int c = inv_perm_col(p);
        g_xp[i] = (c < KDIM) ? tf32r(x[r * KDIM + c]) : 0.0f;
    }
    for (int i = idx; i < KPAD * KPAD; i += stride) {
        int n = i / KPAD, p = i - n * KPAD;
        int k = inv_perm_col(p);
        bool in = (n < KDIM) && (k < KDIM);
        g_W1t[i] = in ? tf32r(W1[k * KDIM + n]) : 0.0f;
        g_W2t[i] = in ? tf32r(W2[k * KDIM + n]) : 0.0f;
    }
    for (int i = idx; i < KPAD; i += stride) {
        g_b1p[i] = (i < KDIM) ? b1[i] : 0.0f;
        g_b2p[i] = (i < KDIM) ? b2[i] : 0.0f;
    }
    for (int i = idx; i < NROWS; i += stride) {
        g_Epos[i] = 0.0f; g_Eneg[i] = 0.0f; g_Lpos[i] = 0.0f; g_ss[i] = 0.0f;
    }
    for (int i = idx; i < NGRP; i += stride) g_cnt[i] = 0;
}

__global__ void hist_kernel(const int* __restrict__ labels)
{
    int i = blockIdx.x * blockDim.x + threadIdx.x;
    if (i < NROWS) atomicAdd(&g_cnt[labels[i]], 1);
}

// ---------------- MLP GEMM: tf32 mma.sync + cp.async, 128x64 tiles ----------------
#define MLP_AW   (128 * SSTR)
#define MLP_BW   (64 * SSTR)
#define MLP_SMEM ((2 * MLP_AW + 2 * MLP_BW) * 4)

template <int MODE>
__global__ __launch_bounds__(256) void mlp_tc_kernel()
{
    const float* __restrict__ A    = (MODE == 0) ? g_xp  : g_h1;
    const float* __restrict__ Bt   = (MODE == 0) ? g_W1t : g_W2t;
    const float* __restrict__ bias = (MODE == 0) ? g_b1p : g_b2p;
    float* __restrict__ C          = (MODE == 0) ? g_h1  : g_f;

    extern __shared__ float sm[];
    const uint32_t sb = smem_u32(sm);
    const uint32_t dA = sb;
    const uint32_t dB = sb + 2 * MLP_AW * 4;

    const int tid  = threadIdx.x;
    const int wid  = tid >> 5;
    const int lane = tid & 31;
    const int g    = lane >> 2;
    const int cl   = lane & 3;
    const int wm   = (wid & 3) * 32;
    const int wn   = (wid >> 2) * 32;
    const int i0   = blockIdx.y * 128;
    const int n0   = blockIdx.x * 64;

    float acc[2][4][4];
#pragma unroll
    for (int mt = 0; mt < 2; mt++)
#pragma unroll
        for (int nt = 0; nt < 4; nt++)
#pragma unroll
            for (int v = 0; v < 4; v++) acc[mt][nt][v] = 0.0f;

    // issue chunk c into buffer b
    auto issue = [&](int c, int b) {
#pragma unroll
        for (int s = 0; s < 4; ++s) {
            int i = tid + 256 * s;
            int row = i >> 3, seg = i & 7;
            cp_async16(dA + (b * MLP_AW + row * SSTR + seg * 4) * 4,
                       A + (size_t)(i0 + row) * KPAD + c * 32 + seg * 4);
        }
#pragma unroll
        for (int s = 0; s < 2; ++s) {
            int i = tid + 256 * s;
            int row = i >> 3, seg = i & 7;
            cp_async16(dB + (b * MLP_BW + row * SSTR + seg * 4) * 4,
                       Bt + (size_t)(n0 + row) * KPAD + c * 32 + seg * 4);
        }
        CP_COMMIT();
    };

    issue(0, 0);
    for (int c = 0; c < NCHUNK; ++c) {
        const int b = c & 1;
        if (c + 1 < NCHUNK) { issue(c + 1, 1 - b); CP_WAIT(1); }
        else                { CP_WAIT(0); }
        __syncthreads();
        const float* Ab = sm + b * MLP_AW;
        const float* Bb = sm + 2 * MLP_AW + b * MLP_BW;
#pragma unroll
        for (int kp = 0; kp < 2; ++kp) {
            uint4 a00 = *(const uint4*)(Ab + (wm + g)      * SSTR + cl * 8 + kp * 4);
            uint4 a01 = *(const uint4*)(Ab + (wm + g + 8)  * SSTR + cl * 8 + kp * 4);
            uint4 a10 = *(const uint4*)(Ab + (wm + g + 16) * SSTR + cl * 8 + kp * 4);
            uint4 a11 = *(const uint4*)(Ab + (wm + g + 24) * SSTR + cl * 8 + kp * 4);
#pragma unroll
            for (int nt = 0; nt < 4; ++nt) {
                uint4 bv = *(const uint4*)(Bb + (wn + nt * 8 + g) * SSTR + cl * 8 + kp * 4);
                uint32_t af0[4] = { a00.x, a01.x, a00.y, a01.y };
                uint32_t af1[4] = { a10.x, a11.x, a10.y, a11.y };
                uint32_t bf0[2] = { bv.x, bv.y };
                mma_tf32(acc[0][nt], af0, bf0);
                mma_tf32(acc[1][nt], af1, bf0);
                uint32_t af0b[4] = { a00.z, a01.z, a00.w, a01.w };
                uint32_t af1b[4] = { a10.z, a11.z, a10.w, a11.w };
                uint32_t bf1[2] = { bv.z, bv.w };
                mma_tf32(acc[0][nt], af0b, bf1);
                mma_tf32(acc[1][nt], af1b, bf1);
            }
        }
        __syncthreads();
    }

    // epilogue: bias (+relu), permuted scatter store; MODE 1 adds row sum-of-squares
#pragma unroll
    for (int mt = 0; mt < 2; ++mt) {
#pragma unroll
        for (int h = 0; h < 2; ++h) {
            const int r = i0 + wm + mt * 16 + h * 8 + g;
            float ssum = 0.0f;
#pragma unroll
            for (int nt = 0; nt < 4; ++nt) {
                const int col = n0 + wn + nt * 8 + 2 * cl;
                float v0 = acc[mt][nt][h * 2 + 0] + bias[col];
                float v1 = acc[mt][nt][h * 2 + 1] + bias[col + 1];
                if (MODE == 0) {
                    v0 = tf32r(fmaxf(v0, 0.0f));
                    v1 = tf32r(fmaxf(v1, 0.0f));
                }
                C[(size_t)r * KPAD + perm_col(col)]     = v0;
                C[(size_t)r * KPAD + perm_col(col + 1)] = v1;
                if (MODE == 1) ssum = fmaf(v0, v0, fmaf(v1, v1, ssum));
            }
            if (MODE == 1) {
                ssum += __shfl_xor_sync(0xffffffffu, ssum, 1);
                ssum += __shfl_xor_sync(0xffffffffu, ssum, 2);
                if (cl == 0) atomicAdd(&g_ss[r], ssum);
            }
        }
    }
}

// ---------------- row scale by rsqrt(ss) + tf32 round ----------------
__global__ void norm_kernel()
{
    int idx = blockIdx.x * blockDim.x + threadIdx.x;   // float4 index
    const int total = NROWS * (KPAD / 4);
    if (idx < total) {
        int row = idx / (KPAD / 4);
        float inv = rsqrtf(g_ss[row]);
        float4 v = ((const float4*)g_f)[idx];
        v.x = tf32r(v.x * inv); v.y = tf32r(v.y * inv);
        v.z = tf32r(v.z * inv); v.w = tf32r(v.w * inv);
        ((float4*)g_f)[idx] = v;
    }
}

// ---------------- contrast kernel: tf32 mma.sync + cp.async, triangular grid ----------------
#define CON_SMEM_BYTES ((4 * BUFW) * 4 + 256 * 4 + 768 * 4)

__global__ __launch_bounds__(256) void contrast_mma_kernel(const int* __restrict__ labels)
{
    // triangular decode: blockIdx.x in [0, 2080) -> (bi, bj) with bj >= bi
    int v = 2079 - (int)blockIdx.x;
    int t = (int)((sqrtf(8.0f * v + 1.0f) - 1.0f) * 0.5f);
    while ((t + 1) * (t + 2) / 2 <= v) ++t;
    while (t * (t + 1) / 2 > v) --t;
    const int bi = 63 - t;
    const int bj = 63 - (v - t * (t + 1) / 2);
    const int i0 = bi * 128, j0 = bj * 128;
    const bool diag = (bi == bj);

    extern __shared__ float sm[];
    const uint32_t sb = smem_u32(sm);
    const uint32_t dA = sb;
    const uint32_t dB = sb + 2 * BUFW * 4;
    int*   labi_s = (int*)(sm + 4 * BUFW);
    int*   labj_s = labi_s + 128;
    float* rEp = (float*)(labj_s + 128);
    float* rEn = rEp + 128;
    float* rLp = rEp + 256;
    float* cEp = rEp + 384;
    float* cEn = rEp + 512;
    float* cLp = rEp + 640;

    const int tid  = threadIdx.x;
    const int wid  = tid >> 5;
    const int lane = tid & 31;
    const int g    = lane >> 2;
    const int cl   = lane & 3;
    const int wm   = (wid & 3) * 32;
    const int wn   = (wid >> 2) * 64;

    if (tid < 128) labi_s[tid] = labels[i0 + tid];
    else           labj_s[tid - 128] = labels[j0 + tid - 128];
    for (int q = tid; q < 768; q += 256) rEp[q] = 0.0f;

    auto issue = [&](int c, int b) {
#pragma unroll
        for (int s = 0; s < 4; ++s) {
            int i = tid + 256 * s;
            int row = i >> 3, seg = i & 7;
            uint32_t off = (b * BUFW + row * SSTR + seg * 4) * 4;
            cp_async16(dA + off, g_f + (size_t)(i0 + row) * KPAD + c * 32 + seg * 4);
            cp_async16(dB + off, g_f + (size_t)(j0 + row) * KPAD + c * 32 + seg * 4);
        }
        CP_COMMIT();
    };

    float acc[2][8][4];
#pragma unroll
    for (int mt = 0; mt < 2; mt++)
#pragma unroll
        for (int nt = 0; nt < 8; nt++)
#pragma unroll
            for (int u = 0; u < 4; u++) acc[mt][nt][u] = 0.0f;

    issue(0, 0);
    for (int c = 0; c < NCHUNK; ++c) {
        const int b = c & 1;
        if (c + 1 < NCHUNK) { issue(c + 1, 1 - b); CP_WAIT(1); }
        else                { CP_WAIT(0); }
        __syncthreads();
        const float* A = sm + b * BUFW;
        const float* B = sm + 2 * BUFW + b * BUFW;
#pragma unroll
        for (int kp = 0; kp < 2; ++kp) {
            uint4 a00 = *(const uint4*)(A + (wm + g)      * SSTR + cl * 8 + kp * 4);
            uint4 a01 = *(const uint4*)(A + (wm + g + 8)  * SSTR + cl * 8 + kp * 4);
            uint4 a10 = *(const uint4*)(A + (wm + g + 16) * SSTR + cl * 8 + kp * 4);
            uint4 a11 = *(const uint4*)(A + (wm + g + 24) * SSTR + cl * 8 + kp * 4);
#pragma unroll
            for (int nt = 0; nt < 8; ++nt) {
                uint4 bv = *(const uint4*)(B + (wn + nt * 8 + g) * SSTR + cl * 8 + kp * 4);
                uint32_t af0[4] = { a00.x, a01.x, a00.y, a01.y };
                uint32_t af1[4] = { a10.x, a11.x, a10.y, a11.y };
                uint32_t bf0[2] = { bv.x, bv.y };
                mma_tf32(acc[0][nt], af0, bf0);
                mma_tf32(acc[1][nt], af1, bf0);
                uint32_t af0b[4] = { a00.z, a01.z, a00.w, a01.w };
                uint32_t af1b[4] = { a10.z, a11.z, a10.w, a11.w };
                uint32_t bf1[2] = { bv.z, bv.w };
                mma_tf32(acc[0][nt], af0b, bf1);
                mma_tf32(acc[1][nt], af1b, bf1);
            }
        }
        __syncthreads();
    }

    // ---- fused epilogue (row + column accumulation, symmetric) ----
    float rp[4][3];
#pragma unroll
    for (int u = 0; u < 4; u++) { rp[u][0] = 0.f; rp[u][1] = 0.f; rp[u][2] = 0.f; }

#pragma unroll
    for (int nt = 0; nt < 8; ++nt) {
        float cs[2][3] = { {0.f,0.f,0.f}, {0.f,0.f,0.f} };
#pragma unroll
        for (int mt = 0; mt < 2; ++mt)
#pragma unroll
            for (int h = 0; h < 2; ++h)
#pragma unroll
                for (int q = 0; q < 2; ++q) {
                    const int r   = wm + mt * 16 + h * 8 + g;
                    const int col = wn + nt * 8 + 2 * cl + q;
                    float tt = fmaf(acc[mt][nt][h * 2 + q], 100.0f, -100.0f);
                    float e  = __expf(tt);
                    bool self  = diag && (r == col);
                    bool match = (labi_s[r] == labj_s[col]);
                    if (!self) {
                        if (match) { rp[mt * 2 + h][0] += e; rp[mt * 2 + h][2] += tt;
                                     cs[q][0] += e;          cs[q][2] += tt; }
                        else       { rp[mt * 2 + h][1] += e; cs[q][1] += e; }
                    }
                }
        if (!diag) {
#pragma unroll
            for (int q = 0; q < 2; ++q)
#pragma unroll
                for (int u = 0; u < 3; ++u) {
                    float x = cs[q][u];
                    x += __shfl_xor_sync(0xffffffffu, x, 4);
                    x += __shfl_xor_sync(0xffffffffu, x, 8);
                    x += __shfl_xor_sync(0xffffffffu, x, 16);
                    cs[q][u] = x;
                }
            if (g == 0) {
                const int col = wn + nt * 8 + 2 * cl;
                atomicAdd(&cEp[col],     cs[0][0]);
                atomicAdd(&cEn[col],     cs[0][1]);
                atomicAdd(&cLp[col],     cs[0][2]);
                atomicAdd(&cEp[col + 1], cs[1][0]);
                atomicAdd(&cEn[col + 1], cs[1][1]);
                atomicAdd(&cLp[col + 1], cs[1][2]);
            }
        }
    }
#pragma unroll
    for (int u = 0; u < 4; ++u) {
#pragma unroll
        for (int w = 0; w < 3; ++w) {
            float x = rp[u][w];
            x += __shfl_xor_sync(0xffffffffu, x, 1);
            x += __shfl_xor_sync(0xffffffffu, x, 2);
            rp[u][w] = x;
        }
        if (cl == 0) {
            const int r = wm + (u >> 1) * 16 + (u & 1) * 8 + g;
            atomicAdd(&rEp[r], rp[u][0]);
            atomicAdd(&rEn[r], rp[u][1]);
            atomicAdd(&rLp[r], rp[u][2]);
        }
    }
    __syncthreads();
    if (tid < 128) {
        atomicAdd(&g_Epos[i0 + tid], rEp[tid]);
        atomicAdd(&g_Eneg[i0 + tid], rEn[tid]);
        atomicAdd(&g_Lpos[i0 + tid], rLp[tid]);
        if (!diag) {
            atomicAdd(&g_Epos[j0 + tid], cEp[tid]);
            atomicAdd(&g_Eneg[j0 + tid], cEn[tid]);
            atomicAdd(&g_Lpos[j0 + tid], cLp[tid]);
        }
    }
}

// ---------------- final loss reduction ----------------
__global__ void loss_kernel(const int* __restrict__ labels, float* __restrict__ out)
{
    __shared__ float ssum[32], scnt[32];
    int tid = threadIdx.x;
    float local = 0.0f, cnt = 0.0f;
    for (int i = tid; i < NROWS; i += blockDim.x) {
        int pc = g_cnt[labels[i]] - 1;
        if (pc > 0) {
            int nc = NROWS - 1 - pc;
            float fpc = (float)pc;
            float Ep = g_Epos[i], En = g_Eneg[i], Lp = g_Lpos[i];
            float denom = Ep / fpc + ((nc > 0) ? En / (float)nc : En);
            float mean  = Lp / fpc - logf(fpc) - logf(denom);
            local += mean;
            cnt += 1.0f;
        }
    }
#pragma unroll
    for (int off = 16; off > 0; off >>= 1) {
        local += __shfl_down_sync(0xffffffffu, local, off);
        cnt   += __shfl_down_sync(0xffffffffu, cnt, off);
    }
    if ((tid & 31) == 0) { ssum[tid >> 5] = local; scnt[tid >> 5] = cnt; }
    __syncthreads();
    if (tid < 32) {
        int nw = blockDim.x >> 5;
        float a = (tid < nw) ? ssum[tid] : 0.0f;
        float b = (tid < nw) ? scnt[tid] : 0.0f;
#pragma unroll
        for (int off = 16; off > 0; off >>= 1) {
            a += __shfl_down_sync(0xffffffffu, a, off);
            b += __shfl_down_sync(0xffffffffu, b, off);
        }
        if (tid == 0) out[0] = -0.01f * (a / b);
    }
}

// ---------------- launch ----------------
extern "C" void kernel_launch(void* const* d_in, const int* in_sizes, int n_in,
                              void* d_out, int out_size)
{
    const float* x      = (const float*)d_in[0];
    const float* W1     = (const float*)d_in[1];
    const float* b1     = (const float*)d_in[2];
    const float* W2     = (const float*)d_in[3];
    const float* b2     = (const float*)d_in[4];
    const int*   labels = (const int*)d_in[5];
    float* out = (float*)d_out;

    static int smem_set = 0;
    if (!smem_set) {
        cudaFuncSetAttribute(contrast_mma_kernel,
                             cudaFuncAttributeMaxDynamicSharedMemorySize, CON_SMEM_BYTES);
        cudaFuncSetAttribute(mlp_tc_kernel<0>,
                             cudaFuncAttributeMaxDynamicSharedMemorySize, MLP_SMEM);
        cudaFuncSetAttribute(mlp_tc_kernel<1>,
                             cudaFuncAttributeMaxDynamicSharedMemorySize, MLP_SMEM);
        smem_set = 1;
    }

    prep_kernel<<<256, 256>>>(x, W1, b1, W2, b2);
    hist_kernel<<<(NROWS + 255) / 256, 256>>>(labels);

    dim3 gm(KPAD / 64, NROWS / 128);            // (5, 64)
    mlp_tc_kernel<0><<<gm, 256, MLP_SMEM>>>();
    mlp_tc_kernel<1><<<gm, 256, MLP_SMEM>>>();

    norm_kernel<<<(NROWS * (KPAD / 4) + 255) / 256, 256>>>();

    contrast_mma_kernel<<<2080, 256, CON_SMEM_BYTES>>>(labels);

    loss_kernel<<<1, 1024>>>(labels, out);
}

// round 6
// speedup vs baseline: 7.9138x; 1.6017x over previous
#include <cuda_runtime.h>
#include <cuda_fp16.h>
#include <math.h>
#include <stdint.h>

#define NROWS 8192
#define KDIM  300
#define KPAD  320           // 10 chunks of 32
#define NCHUNK 10
#define NGRP  101
#define C1    144.26950408889634f   // 100 * log2(e)
#define LN2   0.6931471805599453f

// ---------------- static device scratch ----------------
__device__ __half g_xh [NROWS * KPAD];   // fp16, k-permuted
__device__ __half g_W1h[KPAD * KPAD];    // transposed [n][k], fp16, k-permuted
__device__ __half g_W2h[KPAD * KPAD];
__device__ float  g_b1p[KPAD];
__device__ float  g_b2p[KPAD];
__device__ __half g_h1h[NROWS * KPAD];   // fp16, k-permuted
__device__ __half g_fh [NROWS * KPAD];   // fp16, k-permuted (unnormalized until norm)
__device__ float  g_ss [NROWS];
__device__ float  g_Epos[NROWS];
__device__ float  g_Eneg[NROWS];
__device__ float  g_Lpos[NROWS];         // log2 units
__device__ int    g_cnt[NGRP];

// ---------------- helpers ----------------
// chunk-local k permutation: k -> stored position
__device__ __forceinline__ int perm_col(int k) {
    return (k & ~31) + ((k & 7) >> 1) * 8 + ((k >> 4) & 1) * 4 + ((k >> 3) & 1) * 2 + (k & 1);
}
// stored position -> k
__device__ __forceinline__ int inv_perm_col(int p) {
    int q = p & 31;
    int cl = q >> 3, ks = (q >> 2) & 1, h = (q >> 1) & 1, b = q & 1;
    return (p & ~31) + ks * 16 + h * 8 + cl * 2 + b;
}

__device__ __forceinline__ uint32_t smem_u32(const void* p) {
    uint32_t a;
    asm("{ .reg .u64 t; cvta.to.shared.u64 t, %1; cvt.u32.u64 %0, t; }" : "=r"(a) : "l"(p));
    return a;
}
__device__ __forceinline__ void cp_async16(uint32_t dst, const void* src) {
    asm volatile("cp.async.cg.shared.global [%0], [%1], 16;" :: "r"(dst), "l"(src));
}
#define CP_COMMIT() asm volatile("cp.async.commit_group;" ::: "memory")
#define CP_WAIT(n)  asm volatile("cp.async.wait_group %0;" :: "n"(n) : "memory")

__device__ __forceinline__ void mma_f16(float* d, const uint32_t* a, const uint32_t* b) {
    asm volatile(
        "mma.sync.aligned.m16n8k16.row.col.f32.f16.f16.f32 "
        "{%0,%1,%2,%3}, {%4,%5,%6,%7}, {%8,%9}, {%0,%1,%2,%3};"
        : "+f"(d[0]), "+f"(d[1]), "+f"(d[2]), "+f"(d[3])
        : "r"(a[0]), "r"(a[1]), "r"(a[2]), "r"(a[3]), "r"(b[0]), "r"(b[1]));
}

__device__ __forceinline__ float fast_ex2(float x) {
    float r;
    asm("ex2.approx.ftz.f32 %0, %1;" : "=f"(r) : "f"(x));
    return r;
}

// ---------------- prep: fp16 convert + permute pad; zero accumulators ----------------
__global__ void prep_kernel(const float* __restrict__ x,
                            const float* __restrict__ W1, const float* __restrict__ b1,
                            const float* __restrict__ W2, const float* __restrict__ b2)
{
    int idx = blockIdx.x * blockDim.x + threadIdx.x;
    int stride = gridDim.x * blockDim.x;
    for (int i = idx; i < NROWS * KPAD; i += stride) {
        int r = i / KPAD, p = i - r * KPAD;
        int k = inv_perm_col(p);
        g_xh[i] = (k < KDIM) ? __float2half_rn(x[r * KDIM + k]) : __float2half_rn(0.0f);
    }
    for (int i = idx; i < KPAD * KPAD; i += stride) {
        int n = i / KPAD, p = i - n * KPAD;
        int k = inv_perm_col(p);
        bool in = (n < KDIM) && (k < KDIM);
        g_W1h[i] = in ? __float2half_rn(W1[k * KDIM + n]) : __float2half_rn(0.0f);
        g_W2h[i] = in ? __float2half_rn(W2[k * KDIM + n]) : __float2half_rn(0.0f);
    }
    for (int i = idx; i < KPAD; i += stride) {
        g_b1p[i] = (i < KDIM) ? b1[i] : 0.0f;
        g_b2p[i] = (i < KDIM) ? b2[i] : 0.0f;
    }
    for (int i = idx; i < NROWS; i += stride) {
        g_Epos[i] = 0.0f; g_Eneg[i] = 0.0f; g_Lpos[i] = 0.0f; g_ss[i] = 0.0f;
    }
    for (int i = idx; i < NGRP; i += stride) g_cnt[i] = 0;
}

__global__ void hist_kernel(const int* __restrict__ labels)
{
    int i = blockIdx.x * blockDim.x + threadIdx.x;
    if (i < NROWS) atomicAdd(&g_cnt[labels[i]], 1);
}

// ---------------- MLP GEMM: fp16 mma.sync m16n8k16, 128x64 tiles ----------------
// smem: A 2 x 8192B @0, B 2 x 4096B @16384 ; rows = 64B (32 halves), no pad
#define MLP_SMEM (16384 + 8192)

template <int MODE>
__global__ __launch_bounds__(256) void mlp_tc_kernel()
{
    const __half* __restrict__ A    = (MODE == 0) ? g_xh  : g_h1h;
    const __half* __restrict__ Bt   = (MODE == 0) ? g_W1h : g_W2h;
    const float*  __restrict__ bias = (MODE == 0) ? g_b1p : g_b2p;
    __half* __restrict__ C          = (MODE == 0) ? g_h1h : g_fh;

    extern __shared__ char smc[];
    const uint32_t sb = smem_u32(smc);

    const int tid  = threadIdx.x;
    const int wid  = tid >> 5;
    const int lane = tid & 31;
    const int g    = lane >> 2;
    const int cl   = lane & 3;
    const int wm   = (wid & 3) * 32;
    const int wn   = (wid >> 2) * 32;
    const int i0   = blockIdx.y * 128;
    const int n0   = blockIdx.x * 64;

    float acc[2][4][4];
#pragma unroll
    for (int mt = 0; mt < 2; mt++)
#pragma unroll
        for (int nt = 0; nt < 4; nt++)
#pragma unroll
            for (int v = 0; v < 4; v++) acc[mt][nt][v] = 0.0f;

    auto issue = [&](int c, int b) {
#pragma unroll
        for (int s = 0; s < 2; ++s) {
            int i = tid + 256 * s;
            int row = i >> 2, seg = i & 3;
            cp_async16(sb + b * 8192 + row * 64 + seg * 16,
                       A + (size_t)(i0 + row) * KPAD + c * 32 + seg * 8);
        }
        {
            int row = tid >> 2, seg = tid & 3;
            cp_async16(sb + 16384 + b * 4096 + row * 64 + seg * 16,
                       Bt + (size_t)(n0 + row) * KPAD + c * 32 + seg * 8);
        }
        CP_COMMIT();
    };

    issue(0, 0);
    for (int c = 0; c < NCHUNK; ++c) {
        const int b = c & 1;
        if (c + 1 < NCHUNK) { issue(c + 1, 1 - b); CP_WAIT(1); }
        else                { CP_WAIT(0); }
        __syncthreads();
        const char* Ab = smc + b * 8192;
        const char* Bb = smc + 16384 + b * 4096;
        uint4 qa[4];
#pragma unroll
        for (int r = 0; r < 4; ++r)
            qa[r] = *(const uint4*)(Ab + (wm + r * 8 + g) * 64 + cl * 16);
#pragma unroll
        for (int nt = 0; nt < 4; ++nt) {
            uint4 bv = *(const uint4*)(Bb + (wn + nt * 8 + g) * 64 + cl * 16);
            uint32_t a0[4] = { qa[0].x, qa[1].x, qa[0].y, qa[1].y };
            uint32_t a1[4] = { qa[2].x, qa[3].x, qa[2].y, qa[3].y };
            uint32_t b0[2] = { bv.x, bv.y };
            mma_f16(acc[0][nt], a0, b0);
            mma_f16(acc[1][nt], a1, b0);
            uint32_t a0b[4] = { qa[0].z, qa[1].z, qa[0].w, qa[1].w };
            uint32_t a1b[4] = { qa[2].z, qa[3].z, qa[2].w, qa[3].w };
            uint32_t b1[2] = { bv.z, bv.w };
            mma_f16(acc[0][nt], a0b, b1);
            mma_f16(acc[1][nt], a1b, b1);
        }
        __syncthreads();
    }

    // epilogue: bias (+relu), half2 store to permuted positions
#pragma unroll
    for (int mt = 0; mt < 2; ++mt) {
#pragma unroll
        for (int h = 0; h < 2; ++h) {
            const int r = i0 + wm + mt * 16 + h * 8 + g;
            float ssum = 0.0f;
#pragma unroll
            for (int nt = 0; nt < 4; ++nt) {
                const int col = n0 + wn + nt * 8 + 2 * cl;
                float v0 = acc[mt][nt][h * 2 + 0] + bias[col];
                float v1 = acc[mt][nt][h * 2 + 1] + bias[col + 1];
                if (MODE == 0) { v0 = fmaxf(v0, 0.0f); v1 = fmaxf(v1, 0.0f); }
                const int pc = perm_col(col);   // col even -> (pc, pc+1) adjacent
                *(__half2*)(C + (size_t)r * KPAD + pc) = __floats2half2_rn(v0, v1);
                if (MODE == 1) ssum = fmaf(v0, v0, fmaf(v1, v1, ssum));
            }
            if (MODE == 1) {
                ssum += __shfl_xor_sync(0xffffffffu, ssum, 1);
                ssum += __shfl_xor_sync(0xffffffffu, ssum, 2);
                if (cl == 0) atomicAdd(&g_ss[r], ssum);
            }
        }
    }
}

// ---------------- row scale by rsqrt(ss), fp16 in place ----------------
__global__ void norm_kernel()
{
    int idx = blockIdx.x * blockDim.x + threadIdx.x;   // 8 halves per thread
    const int total = NROWS * (KPAD / 8);
    if (idx < total) {
        int row = idx / (KPAD / 8);
        float inv = rsqrtf(g_ss[row]);
        uint4 v = ((const uint4*)g_fh)[idx];
        __half2* h = (__half2*)&v;
#pragma unroll
        for (int q = 0; q < 4; ++q) {
            float2 f = __half22float2(h[q]);
            h[q] = __floats2half2_rn(f.x * inv, f.y * inv);
        }
        ((uint4*)g_fh)[idx] = v;
    }
}

// ---------------- contrast kernel: fp16 mma.sync, triangular grid ----------------
// smem: bufA 2x8192 @0, bufB 2x8192 @16384, labi @32768, labj @33280, partials @33792
#define CON_SMEM_BYTES (33792 + 6 * 512)

__global__ __launch_bounds__(256) void contrast_mma_kernel(const int* __restrict__ labels)
{
    int v = 2079 - (int)blockIdx.x;
    int t = (int)((sqrtf(8.0f * v + 1.0f) - 1.0f) * 0.5f);
    while ((t + 1) * (t + 2) / 2 <= v) ++t;
    while (t * (t + 1) / 2 > v) --t;
    const int bi = 63 - t;
    const int bj = 63 - (v - t * (t + 1) / 2);
    const int i0 = bi * 128, j0 = bj * 128;
    const bool diag = (bi == bj);

    extern __shared__ char smc[];
    const uint32_t sb = smem_u32(smc);
    int*   labi_s = (int*)(smc + 32768);
    int*   labj_s = (int*)(smc + 33280);
    float* rEp = (float*)(smc + 33792);
    float* rEn = rEp + 128;
    float* rLp = rEp + 256;
    float* cEp = rEp + 384;
    float* cEn = rEp + 512;
    float* cLp = rEp + 640;

    const int tid  = threadIdx.x;
    const int wid  = tid >> 5;
    const int lane = tid & 31;
    const int g    = lane >> 2;
    const int cl   = lane & 3;
    const int wm   = (wid & 3) * 32;
    const int wn   = (wid >> 2) * 64;

    auto issue = [&](int c, int b) {
#pragma unroll
        for (int s = 0; s < 2; ++s) {
            int i = tid + 256 * s;
            int row = i >> 2, seg = i & 3;
            uint32_t off = b * 8192 + row * 64 + seg * 16;
            cp_async16(sb + off,         g_fh + (size_t)(i0 + row) * KPAD + c * 32 + seg * 8);
            cp_async16(sb + 16384 + off, g_fh + (size_t)(j0 + row) * KPAD + c * 32 + seg * 8);
        }
        CP_COMMIT();
    };

    issue(0, 0);
    if (tid < 128) labi_s[tid] = labels[i0 + tid];
    else           labj_s[tid - 128] = labels[j0 + tid - 128];
    for (int q = tid; q < 768; q += 256) rEp[q] = 0.0f;

    float acc[2][8][4];
#pragma unroll
    for (int mt = 0; mt < 2; mt++)
#pragma unroll
        for (int nt = 0; nt < 8; nt++)
#pragma unroll
            for (int u = 0; u < 4; u++) acc[mt][nt][u] = 0.0f;

    for (int c = 0; c < NCHUNK; ++c) {
        const int b = c & 1;
        if (c + 1 < NCHUNK) { issue(c + 1, 1 - b); CP_WAIT(1); }
        else                { CP_WAIT(0); }
        __syncthreads();
        const char* Ab = smc + b * 8192;
        const char* Bb = smc + 16384 + b * 8192;
        uint4 qa[4];
#pragma unroll
        for (int r = 0; r < 4; ++r)
            qa[r] = *(const uint4*)(Ab + (wm + r * 8 + g) * 64 + cl * 16);
#pragma unroll
        for (int nt = 0; nt < 8; ++nt) {
            uint4 bv = *(const uint4*)(Bb + (wn + nt * 8 + g) * 64 + cl * 16);
            uint32_t a0[4] = { qa[0].x, qa[1].x, qa[0].y, qa[1].y };
            uint32_t a1[4] = { qa[2].x, qa[3].x, qa[2].y, qa[3].y };
            uint32_t b0[2] = { bv.x, bv.y };
            mma_f16(acc[0][nt], a0, b0);
            mma_f16(acc[1][nt], a1, b0);
            uint32_t a0b[4] = { qa[0].z, qa[1].z, qa[0].w, qa[1].w };
            uint32_t a1b[4] = { qa[2].z, qa[3].z, qa[2].w, qa[3].w };
            uint32_t b1[2] = { bv.z, bv.w };
            mma_f16(acc[0][nt], a0b, b1);
            mma_f16(acc[1][nt], a1b, b1);
        }
        __syncthreads();
    }

    // ---- fused epilogue: t2 = 100*log2e*(s-1); e = 2^t2; Lp kept in log2 units ----
    float rp[4][3];
#pragma unroll
    for (int u = 0; u < 4; u++) { rp[u][0] = 0.f; rp[u][1] = 0.f; rp[u][2] = 0.f; }

#pragma unroll
    for (int nt = 0; nt < 8; ++nt) {
        float cs[2][3] = { {0.f,0.f,0.f}, {0.f,0.f,0.f} };
#pragma unroll
        for (int mt = 0; mt < 2; ++mt)
#pragma unroll
            for (int h = 0; h < 2; ++h)
#pragma unroll
                for (int q = 0; q < 2; ++q) {
                    const int r   = wm + mt * 16 + h * 8 + g;
                    const int col = wn + nt * 8 + 2 * cl + q;
                    float t2 = fmaf(acc[mt][nt][h * 2 + q], C1, -C1);
                    float e  = fast_ex2(t2);
                    bool self  = diag && (r == col);
                    bool match = (labi_s[r] == labj_s[col]);
                    if (!self) {
                        if (match) { rp[mt * 2 + h][0] += e; rp[mt * 2 + h][2] += t2;
                                     cs[q][0] += e;          cs[q][2] += t2; }
                        else       { rp[mt * 2 + h][1] += e; cs[q][1] += e; }
                    }
                }
        if (!diag) {
#pragma unroll
            for (int q = 0; q < 2; ++q)
#pragma unroll
                for (int u = 0; u < 3; ++u) {
                    float x = cs[q][u];
                    x += __shfl_xor_sync(0xffffffffu, x, 4);
                    x += __shfl_xor_sync(0xffffffffu, x, 8);
                    x += __shfl_xor_sync(0xffffffffu, x, 16);
                    cs[q][u] = x;
                }
            if (g == 0) {
                const int col = wn + nt * 8 + 2 * cl;
                atomicAdd(&cEp[col],     cs[0][0]);
                atomicAdd(&cEn[col],     cs[0][1]);
                atomicAdd(&cLp[col],     cs[0][2]);
                atomicAdd(&cEp[col + 1], cs[1][0]);
                atomicAdd(&cEn[col + 1], cs[1][1]);
                atomicAdd(&cLp[col + 1], cs[1][2]);
            }
        }
    }
#pragma unroll
    for (int u = 0; u < 4; ++u) {
#pragma unroll
        for (int w = 0; w < 3; ++w) {
            float x = rp[u][w];
            x += __shfl_xor_sync(0xffffffffu, x, 1);
            x += __shfl_xor_sync(0xffffffffu, x, 2);
            rp[u][w] = x;
        }
        if (cl == 0) {
            const int r = wm + (u >> 1) * 16 + (u & 1) * 8 + g;
            atomicAdd(&rEp[r], rp[u][0]);
            atomicAdd(&rEn[r], rp[u][1]);
            atomicAdd(&rLp[r], rp[u][2]);
        }
    }
    __syncthreads();
    if (tid < 128) {
        atomicAdd(&g_Epos[i0 + tid], rEp[tid]);
        atomicAdd(&g_Eneg[i0 + tid], rEn[tid]);
        atomicAdd(&g_Lpos[i0 + tid], rLp[tid]);
        if (!diag) {
            atomicAdd(&g_Epos[j0 + tid], cEp[tid]);
            atomicAdd(&g_Eneg[j0 + tid], cEn[tid]);
            atomicAdd(&g_Lpos[j0 + tid], cLp[tid]);
        }
    }
}

// ---------------- final loss reduction (Lp arrives in log2 units) ----------------
__global__ void loss_kernel(const int* __restrict__ labels, float* __restrict__ out)
{
    __shared__ float ssum[32], scnt[32];
    int tid = threadIdx.x;
    float local = 0.0f, cnt = 0.0f;
    for (int i = tid; i < NROWS; i += blockDim.x) {
        int pc = g_cnt[labels[i]] - 1;
        if (pc > 0) {
            int nc = NROWS - 1 - pc;
            float fpc = (float)pc;
            float Ep = g_Epos[i], En = g_Eneg[i], Lp = g_Lpos[i] * LN2;
            float denom = Ep / fpc + ((nc > 0) ? En / (float)nc : En);
            float mean  = Lp / fpc - logf(fpc) - logf(denom);
            local += mean;
            cnt += 1.0f;
        }
    }
#pragma unroll
    for (int off = 16; off > 0; off >>= 1) {
        local += __shfl_down_sync(0xffffffffu, local, off);
        cnt   += __shfl_down_sync(0xffffffffu, cnt, off);
    }
    if ((tid & 31) == 0) { ssum[tid >> 5] = local; scnt[tid >> 5] = cnt; }
    __syncthreads();
    if (tid < 32) {
        int nw = blockDim.x >> 5;
        float a = (tid < nw) ? ssum[tid] : 0.0f;
        float b = (tid < nw) ? scnt[tid] : 0.0f;
#pragma unroll
        for (int off = 16; off > 0; off >>= 1) {
            a += __shfl_down_sync(0xffffffffu, a, off);
            b += __shfl_down_sync(0xffffffffu, b, off);
        }
        if (tid == 0) out[0] = -0.01f * (a / b);
    }
}

// ---------------- launch ----------------
extern "C" void kernel_launch(void* const* d_in, const int* in_sizes, int n_in,
                              void* d_out, int out_size)
{
    const float* x      = (const float*)d_in[0];
    const float* W1     = (const float*)d_in[1];
    const float* b1     = (const float*)d_in[2];
    const float* W2     = (const float*)d_in[3];
    const float* b2     = (const float*)d_in[4];
    const int*   labels = (const int*)d_in[5];
    float* out = (float*)d_out;

    static int smem_set = 0;
    if (!smem_set) {
        cudaFuncSetAttribute(contrast_mma_kernel,
                             cudaFuncAttributeMaxDynamicSharedMemorySize, CON_SMEM_BYTES);
        cudaFuncSetAttribute(mlp_tc_kernel<0>,
                             cudaFuncAttributeMaxDynamicSharedMemorySize, MLP_SMEM);
        cudaFuncSetAttribute(mlp_tc_kernel<1>,
                             cudaFuncAttributeMaxDynamicSharedMemorySize, MLP_SMEM);
        smem_set = 1;
    }

    prep_kernel<<<256, 256>>>(x, W1, b1, W2, b2);
    hist_kernel<<<(NROWS + 255) / 256, 256>>>(labels);

    dim3 gm(KPAD / 64, NROWS / 128);            // (5, 64)
    mlp_tc_kernel<0><<<gm, 256, MLP_SMEM>>>();
    mlp_tc_kernel<1><<<gm, 256, MLP_SMEM>>>();

    norm_kernel<<<(NROWS * (KPAD / 8) + 255) / 256, 256>>>();

    contrast_mma_kernel<<<2080, 256, CON_SMEM_BYTES>>>(labels);

    loss_kernel<<<1, 1024>>>(labels, out);
}

// round 8
// speedup vs baseline: 8.5844x; 1.0847x over previous
#include <cuda_runtime.h>
#include <cuda_fp16.h>
#include <math.h>
#include <stdint.h>

#define NROWS 8192
#define KDIM  300
#define KPAD  320           // 10 chunks of 32
#define NCHUNK 10
#define NGRP  101
#define C1    144.26950408889634f   // 100 * log2(e)
#define LN2   0.6931471805599453f

// ---------------- static device scratch ----------------
__device__ __half g_xh [NROWS * KPAD];   // fp16, k-permuted
__device__ __half g_W1h[KPAD * KPAD];    // transposed [n][k], fp16, k-permuted
__device__ __half g_W2h[KPAD * KPAD];
__device__ float  g_b1p[KPAD];
__device__ float  g_b2p[KPAD];
__device__ __half g_h1h[NROWS * KPAD];   // fp16, k-permuted
__device__ __half g_fh [NROWS * KPAD];   // fp16, k-permuted
__device__ float  g_ss [NROWS];
__device__ float  g_Epos[NROWS];
__device__ float  g_Eneg[NROWS];
__device__ float  g_Lpos[NROWS];         // log2 units
__device__ int    g_cnt[NGRP];

// ---------------- helpers ----------------
__device__ __forceinline__ int perm_col(int k) {
    return (k & ~31) + ((k & 7) >> 1) * 8 + ((k >> 4) & 1) * 4 + ((k >> 3) & 1) * 2 + (k & 1);
}
__device__ __forceinline__ int inv_perm_col(int p) {
    int q = p & 31;
    int cl = q >> 3, ks = (q >> 2) & 1, h = (q >> 1) & 1, b = q & 1;
    return (p & ~31) + ks * 16 + h * 8 + cl * 2 + b;
}

__device__ __forceinline__ uint32_t smem_u32(const void* p) {
    uint32_t a;
    asm("{ .reg .u64 t; cvta.to.shared.u64 t, %1; cvt.u32.u64 %0, t; }" : "=r"(a) : "l"(p));
    return a;
}
__device__ __forceinline__ void cp_async16(uint32_t dst, const void* src) {
    asm volatile("cp.async.cg.shared.global [%0], [%1], 16;" :: "r"(dst), "l"(src));
}
#define CP_COMMIT() asm volatile("cp.async.commit_group;" ::: "memory")
#define CP_WAIT(n)  asm volatile("cp.async.wait_group %0;" :: "n"(n) : "memory")

__device__ __forceinline__ void mma_f16(float* d, const uint32_t* a, const uint32_t* b) {
    asm volatile(
        "mma.sync.aligned.m16n8k16.row.col.f32.f16.f16.f32 "
        "{%0,%1,%2,%3}, {%4,%5,%6,%7}, {%8,%9}, {%0,%1,%2,%3};"
        : "+f"(d[0]), "+f"(d[1]), "+f"(d[2]), "+f"(d[3])
        : "r"(a[0]), "r"(a[1]), "r"(a[2]), "r"(a[3]), "r"(b[0]), "r"(b[1]));
}

__device__ __forceinline__ float fast_ex2(float x) {
    float r;
    asm("ex2.approx.ftz.f32 %0, %1;" : "=f"(r) : "f"(x));
    return r;
}

// ---------------- prep: vectorized fp16 convert + permute ----------------
__global__ void prep_kernel(const float* __restrict__ x,
                            const float* __restrict__ W1, const float* __restrict__ b1,
                            const float* __restrict__ W2, const float* __restrict__ b2)
{
    int idx = blockIdx.x * blockDim.x + threadIdx.x;
    int stride = gridDim.x * blockDim.x;
    const int VR = KPAD / 8;   // 40 vectors per row

    // x -> g_xh : one uint4 (8 halves) per iteration
    for (int vec = idx; vec < NROWS * VR; vec += stride) {
        int r = vec / VR, p0 = (vec - r * VR) * 8;
        __half h[8];
#pragma unroll
        for (int q = 0; q < 8; ++q) {
            int k = inv_perm_col(p0 + q);
            h[q] = (k < KDIM) ? __float2half_rn(x[r * KDIM + k]) : __ushort_as_half(0);
        }
        ((uint4*)g_xh)[vec] = *(uint4*)h;
    }
    // W1, W2 -> transposed fp16
    for (int vec = idx; vec < KPAD * VR; vec += stride) {
        int n = vec / VR, p0 = (vec - n * VR) * 8;
        __half h1[8], h2[8];
#pragma unroll
        for (int q = 0; q < 8; ++q) {
            int k = inv_perm_col(p0 + q);
            bool in = (n < KDIM) && (k < KDIM);
            h1[q] = in ? __float2half_rn(W1[k * KDIM + n]) : __ushort_as_half(0);
            h2[q] = in ? __float2half_rn(W2[k * KDIM + n]) : __ushort_as_half(0);
        }
        ((uint4*)g_W1h)[vec] = *(uint4*)h1;
        ((uint4*)g_W2h)[vec] = *(uint4*)h2;
    }
    for (int i = idx; i < KPAD; i += stride) {
        g_b1p[i] = (i < KDIM) ? b1[i] : 0.0f;
        g_b2p[i] = (i < KDIM) ? b2[i] : 0.0f;
    }
    for (int i = idx; i < NROWS; i += stride) {
        g_Epos[i] = 0.0f; g_Eneg[i] = 0.0f; g_Lpos[i] = 0.0f; g_ss[i] = 0.0f;
    }
    for (int i = idx; i < NGRP; i += stride) g_cnt[i] = 0;
}

__global__ void hist_kernel(const int* __restrict__ labels)
{
    int i = blockIdx.x * blockDim.x + threadIdx.x;
    if (i < NROWS) atomicAdd(&g_cnt[labels[i]], 1);
}

// ---------------- MLP GEMM: 64x64 tiles, 128 threads, 3-stage ----------------
// stage = A 4KB + B 4KB = 8KB; 3 stages = 24KB
#define MLP_SMEM (3 * 8192)

template <int MODE>
__global__ __launch_bounds__(128) void mlp_tc_kernel()
{
    const __half* __restrict__ A    = (MODE == 0) ? g_xh  : g_h1h;
    const __half* __restrict__ Bt   = (MODE == 0) ? g_W1h : g_W2h;
    const float*  __restrict__ bias = (MODE == 0) ? g_b1p : g_b2p;
    __half* __restrict__ C          = (MODE == 0) ? g_h1h : g_fh;

    extern __shared__ char smc[];
    const uint32_t sb = smem_u32(smc);

    const int tid  = threadIdx.x;
    const int wid  = tid >> 5;
    const int lane = tid & 31;
    const int g    = lane >> 2;
    const int cl   = lane & 3;
    const int wm   = (wid & 1) * 32;
    const int wn   = (wid >> 1) * 32;
    const int i0   = blockIdx.y * 64;
    const int n0   = blockIdx.x * 64;

    float acc[2][4][4];
#pragma unroll
    for (int mt = 0; mt < 2; mt++)
#pragma unroll
        for (int nt = 0; nt < 4; nt++)
#pragma unroll
            for (int v = 0; v < 4; v++) acc[mt][nt][v] = 0.0f;

    auto issue = [&](int c, int b) {
#pragma unroll
        for (int s = 0; s < 2; ++s) {
            int i = tid + 128 * s;
            int row = i >> 2, seg = i & 3;
            cp_async16(sb + b * 8192 + row * 64 + seg * 16,
                       A + (size_t)(i0 + row) * KPAD + c * 32 + seg * 8);
        }
#pragma unroll
        for (int s = 0; s < 2; ++s) {
            int i = tid + 128 * s;
            int row = i >> 2, seg = i & 3;
            cp_async16(sb + b * 8192 + 4096 + row * 64 + seg * 16,
                       Bt + (size_t)(n0 + row) * KPAD + c * 32 + seg * 8);
        }
        CP_COMMIT();
    };

    issue(0, 0);
    issue(1, 1);
    int bc = 0, bw = 2;
    for (int c = 0; c < NCHUNK; ++c) {
        if (c + 1 < NCHUNK) CP_WAIT(1); else CP_WAIT(0);
        __syncthreads();
        if (c + 2 < NCHUNK) issue(c + 2, bw);
        bw = (bw == 2) ? 0 : bw + 1;
        const char* Ab = smc + bc * 8192;
        const char* Bb = smc + bc * 8192 + 4096;
        bc = (bc == 2) ? 0 : bc + 1;
        uint4 qa[4];
#pragma unroll
        for (int r = 0; r < 4; ++r)
            qa[r] = *(const uint4*)(Ab + (wm + r * 8 + g) * 64 + cl * 16);
#pragma unroll
        for (int nt = 0; nt < 4; ++nt) {
            uint4 bv = *(const uint4*)(Bb + (wn + nt * 8 + g) * 64 + cl * 16);
            uint32_t a0[4] = { qa[0].x, qa[1].x, qa[0].y, qa[1].y };
            uint32_t a1[4] = { qa[2].x, qa[3].x, qa[2].y, qa[3].y };
            uint32_t b0[2] = { bv.x, bv.y };
            mma_f16(acc[0][nt], a0, b0);
            mma_f16(acc[1][nt], a1, b0);
            uint32_t a0b[4] = { qa[0].z, qa[1].z, qa[0].w, qa[1].w };
            uint32_t a1b[4] = { qa[2].z, qa[3].z, qa[2].w, qa[3].w };
            uint32_t b1[2] = { bv.z, bv.w };
            mma_f16(acc[0][nt], a0b, b1);
            mma_f16(acc[1][nt], a1b, b1);
        }
    }

#pragma unroll
    for (int mt = 0; mt < 2; ++mt) {
#pragma unroll
        for (int h = 0; h < 2; ++h) {
            const int r = i0 + wm + mt * 16 + h * 8 + g;
            float ssum = 0.0f;
#pragma unroll
            for (int nt = 0; nt < 4; ++nt) {
                const int col = n0 + wn + nt * 8 + 2 * cl;
                float v0 = acc[mt][nt][h * 2 + 0] + bias[col];
                float v1 = acc[mt][nt][h * 2 + 1] + bias[col + 1];
                if (MODE == 0) { v0 = fmaxf(v0, 0.0f); v1 = fmaxf(v1, 0.0f); }
                const int pc = perm_col(col);
                *(__half2*)(C + (size_t)r * KPAD + pc) = __floats2half2_rn(v0, v1);
                if (MODE == 1) ssum = fmaf(v0, v0, fmaf(v1, v1, ssum));
            }
            if (MODE == 1) {
                ssum += __shfl_xor_sync(0xffffffffu, ssum, 1);
                ssum += __shfl_xor_sync(0xffffffffu, ssum, 2);
                if (cl == 0) atomicAdd(&g_ss[r], ssum);
            }
        }
    }
}

// ---------------- row scale by rsqrt(ss), fp16 in place ----------------
__global__ void norm_kernel()
{
    int idx = blockIdx.x * blockDim.x + threadIdx.x;
    const int total = NROWS * (KPAD / 8);
    if (idx < total) {
        int row = idx / (KPAD / 8);
        float inv = rsqrtf(g_ss[row]);
        uint4 v = ((const uint4*)g_fh)[idx];
        __half2* h = (__half2*)&v;
#pragma unroll
        for (int q = 0; q < 4; ++q) {
            float2 f = __half22float2(h[q]);
            h[q] = __floats2half2_rn(f.x * inv, f.y * inv);
        }
        ((uint4*)g_fh)[idx] = v;
    }
}

// ---------------- contrast kernel: fp16 mma, 3-stage, triangular ----------------
// stage = A 8KB + B 8KB = 16KB; 3 stages = 48KB; labels @49152; partials @50176
#define CON_SMEM_BYTES (49152 + 1024 + 768 * 4)

__global__ __launch_bounds__(256) void contrast_mma_kernel(const int* __restrict__ labels)
{
    int v = 2079 - (int)blockIdx.x;
    int t = (int)((sqrtf(8.0f * v + 1.0f) - 1.0f) * 0.5f);
    while ((t + 1) * (t + 2) / 2 <= v) ++t;
    while (t * (t + 1) / 2 > v) --t;
    const int bi = 63 - t;
    const int bj = 63 - (v - t * (t + 1) / 2);
    const int i0 = bi * 128, j0 = bj * 128;
    const bool diag = (bi == bj);

    extern __shared__ char smc[];
    const uint32_t sb = smem_u32(smc);
    int*   labi_s = (int*)(smc + 49152);
    int*   labj_s = (int*)(smc + 49664);
    float* rEp = (float*)(smc + 50176);
    float* rEn = rEp + 128;
    float* rLp = rEp + 256;
    float* cEp = rEp + 384;
    float* cEn = rEp + 512;
    float* cLp = rEp + 640;

    const int tid  = threadIdx.x;
    const int wid  = tid >> 5;
    const int lane = tid & 31;
    const int g    = lane >> 2;
    const int cl   = lane & 3;
    const int wm   = (wid & 3) * 32;
    const int wn   = (wid >> 2) * 64;

    auto issue = [&](int c, int b) {
#pragma unroll
        for (int s = 0; s < 2; ++s) {
            int i = tid + 256 * s;
            int row = i >> 2, seg = i & 3;
            uint32_t off = b * 16384 + row * 64 + seg * 16;
            cp_async16(sb + off,        g_fh + (size_t)(i0 + row) * KPAD + c * 32 + seg * 8);
            cp_async16(sb + 8192 + off, g_fh + (size_t)(j0 + row) * KPAD + c * 32 + seg * 8);
        }
        CP_COMMIT();
    };

    issue(0, 0);
    issue(1, 1);
    if (tid < 128) labi_s[tid] = labels[i0 + tid];
    else           labj_s[tid - 128] = labels[j0 + tid - 128];
    for (int q = tid; q < 768; q += 256) rEp[q] = 0.0f;

    float acc[2][8][4];
#pragma unroll
    for (int mt = 0; mt < 2; mt++)
#pragma unroll
        for (int nt = 0; nt < 8; nt++)
#pragma unroll
            for (int u = 0; u < 4; u++) acc[mt][nt][u] = 0.0f;

    int bc = 0, bw = 2;
    for (int c = 0; c < NCHUNK; ++c) {
        if (c + 1 < NCHUNK) CP_WAIT(1); else CP_WAIT(0);
        __syncthreads();
        if (c + 2 < NCHUNK) issue(c + 2, bw);
        bw = (bw == 2) ? 0 : bw + 1;
        const char* Ab = smc + bc * 16384;
        const char* Bb = smc + bc * 16384 + 8192;
        bc = (bc == 2) ? 0 : bc + 1;
        uint4 qa[4];
#pragma unroll
        for (int r = 0; r < 4; ++r)
            qa[r] = *(const uint4*)(Ab + (wm + r * 8 + g) * 64 + cl * 16);
#pragma unroll
        for (int nt = 0; nt < 8; ++nt) {
            uint4 bv = *(const uint4*)(Bb + (wn + nt * 8 + g) * 64 + cl * 16);
            uint32_t a0[4] = { qa[0].x, qa[1].x, qa[0].y, qa[1].y };
            uint32_t a1[4] = { qa[2].x, qa[3].x, qa[2].y, qa[3].y };
            uint32_t b0[2] = { bv.x, bv.y };
            mma_f16(acc[0][nt], a0, b0);
            mma_f16(acc[1][nt], a1, b0);
            uint32_t a0b[4] = { qa[0].z, qa[1].z, qa[0].w, qa[1].w };
            uint32_t a1b[4] = { qa[2].z, qa[3].z, qa[2].w, qa[3].w };
            uint32_t b1[2] = { bv.z, bv.w };
            mma_f16(acc[0][nt], a0b, b1);
            mma_f16(acc[1][nt], a1b, b1);
        }
    }

    // ---- fused epilogue ----
    float rp[4][3];
#pragma unroll
    for (int u = 0; u < 4; u++) { rp[u][0] = 0.f; rp[u][1] = 0.f; rp[u][2] = 0.f; }

#pragma unroll
    for (int nt = 0; nt < 8; ++nt) {
        float cs[2][3] = { {0.f,0.f,0.f}, {0.f,0.f,0.f} };
#pragma unroll
        for (int mt = 0; mt < 2; ++mt)
#pragma unroll
            for (int h = 0; h < 2; ++h)
#pragma unroll
                for (int q = 0; q < 2; ++q) {
                    const int r   = wm + mt * 16 + h * 8 + g;
                    const int col = wn + nt * 8 + 2 * cl + q;
                    float t2 = fmaf(acc[mt][nt][h * 2 + q], C1, -C1);
                    float e  = fast_ex2(t2);
                    bool self  = diag && (r == col);
                    bool match = (labi_s[r] == labj_s[col]);
                    if (!self) {
                        if (match) { rp[mt * 2 + h][0] += e; rp[mt * 2 + h][2] += t2;
                                     cs[q][0] += e;          cs[q][2] += t2; }
                        else       { rp[mt * 2 + h][1] += e; cs[q][1] += e; }
                    }
                }
        if (!diag) {
#pragma unroll
            for (int q = 0; q < 2; ++q)
#pragma unroll
                for (int u = 0; u < 3; ++u) {
                    float x = cs[q][u];
                    x += __shfl_xor_sync(0xffffffffu, x, 4);
                    x += __shfl_xor_sync(0xffffffffu, x, 8);
                    x += __shfl_xor_sync(0xffffffffu, x, 16);
                    cs[q][u] = x;
                }
            if (g == 0) {
                const int col = wn + nt * 8 + 2 * cl;
                atomicAdd(&cEp[col],     cs[0][0]);
                atomicAdd(&cEn[col],     cs[0][1]);
                atomicAdd(&cLp[col],     cs[0][2]);
                atomicAdd(&cEp[col + 1], cs[1][0]);
                atomicAdd(&cEn[col + 1], cs[1][1]);
                atomicAdd(&cLp[col + 1], cs[1][2]);
            }
        }
    }
#pragma unroll
    for (int u = 0; u < 4; ++u) {
#pragma unroll
        for (int w = 0; w < 3; ++w) {
            float x = rp[u][w];
            x += __shfl_xor_sync(0xffffffffu, x, 1);
            x += __shfl_xor_sync(0xffffffffu, x, 2);
            rp[u][w] = x;
        }
        if (cl == 0) {
            const int r = wm + (u >> 1) * 16 + (u & 1) * 8 + g;
            atomicAdd(&rEp[r], rp[u][0]);
            atomicAdd(&rEn[r], rp[u][1]);
            atomicAdd(&rLp[r], rp[u][2]);
        }
    }
    __syncthreads();
    if (tid < 128) {
        atomicAdd(&g_Epos[i0 + tid], rEp[tid]);
        atomicAdd(&g_Eneg[i0 + tid], rEn[tid]);
        atomicAdd(&g_Lpos[i0 + tid], rLp[tid]);
        if (!diag) {
            atomicAdd(&g_Epos[j0 + tid], cEp[tid]);
            atomicAdd(&g_Eneg[j0 + tid], cEn[tid]);
            atomicAdd(&g_Lpos[j0 + tid], cLp[tid]);
        }
    }
}

// ---------------- final loss reduction (Lp in log2 units) ----------------
__global__ void loss_kernel(const int* __restrict__ labels, float* __restrict__ out)
{
    __shared__ float ssum[32], scnt[32];
    int tid = threadIdx.x;
    float local = 0.0f, cnt = 0.0f;
    for (int i = tid; i < NROWS; i += blockDim.x) {
        int pc = g_cnt[labels[i]] - 1;
        if (pc > 0) {
            int nc = NROWS - 1 - pc;
            float fpc = (float)pc;
            float Ep = g_Epos[i], En = g_Eneg[i], Lp = g_Lpos[i] * LN2;
            float denom = Ep / fpc + ((nc > 0) ? En / (float)nc : En);
            float mean  = Lp / fpc - logf(fpc) - logf(denom);
            local += mean;
            cnt += 1.0f;
        }
    }
#pragma unroll
    for (int off = 16; off > 0; off >>= 1) {
        local += __shfl_down_sync(0xffffffffu, local, off);
        cnt   += __shfl_down_sync(0xffffffffu, cnt, off);
    }
    if ((tid & 31) == 0) { ssum[tid >> 5] = local; scnt[tid >> 5] = cnt; }
    __syncthreads();
    if (tid < 32) {
        int nw = blockDim.x >> 5;
        float a = (tid < nw) ? ssum[tid] : 0.0f;
        float b = (tid < nw) ? scnt[tid] : 0.0f;
#pragma unroll
        for (int off = 16; off > 0; off >>= 1) {
            a += __shfl_down_sync(0xffffffffu, a, off);
            b += __shfl_down_sync(0xffffffffu, b, off);
        }
        if (tid == 0) out[0] = -0.01f * (a / b);
    }
}

// ---------------- launch ----------------
extern "C" void kernel_launch(void* const* d_in, const int* in_sizes, int n_in,
                              void* d_out, int out_size)
{
    const float* x      = (const float*)d_in[0];
    const float* W1     = (const float*)d_in[1];
    const float* b1     = (const float*)d_in[2];
    const float* W2     = (const float*)d_in[3];
    const float* b2     = (const float*)d_in[4];
    const int*   labels = (const int*)d_in[5];
    float* out = (float*)d_out;

    static int smem_set = 0;
    if (!smem_set) {
        cudaFuncSetAttribute(contrast_mma_kernel,
                             cudaFuncAttributeMaxDynamicSharedMemorySize, CON_SMEM_BYTES);
        cudaFuncSetAttribute(mlp_tc_kernel<0>,
                             cudaFuncAttributeMaxDynamicSharedMemorySize, MLP_SMEM);
        cudaFuncSetAttribute(mlp_tc_kernel<1>,
                             cudaFuncAttributeMaxDynamicSharedMemorySize, MLP_SMEM);
        smem_set = 1;
    }

    prep_kernel<<<256, 256>>>(x, W1, b1, W2, b2);
    hist_kernel<<<(NROWS + 255) / 256, 256>>>(labels);

    dim3 gm(KPAD / 64, NROWS / 64);             // (5, 128) = 640 CTAs
    mlp_tc_kernel<0><<<gm, 128, MLP_SMEM>>>();
    mlp_tc_kernel<1><<<gm, 128, MLP_SMEM>>>();

    norm_kernel<<<(NROWS * (KPAD / 8) + 255) / 256, 256>>>();

    contrast_mma_kernel<<<2080, 256, CON_SMEM_BYTES>>>(labels);

    loss_kernel<<<1, 1024>>>(labels, out);
}